// round 1
// baseline (speedup 1.0000x reference)
#include <cuda_runtime.h>
#include <cstddef>

// Problem constants
//  B=4, C_IN=512, H=W=64 -> N=4096, C_QK=256, C_OUT=512
#define NB    4
#define CIN   512
#define NPIX  4096
#define CQK   256
#define COUT  512

// GEMM tiling
#define BM 128
#define BN 128
#define BK 8
#define SLDA 132          // padded smem row stride (floats); 132%32=4 -> conflict-free transpose stores
#define NTHREADS 256

// ---------------------------------------------------------------------------
// Scratch (device globals; no runtime allocation allowed)
// ---------------------------------------------------------------------------
__device__ float g_Q[NB * CQK * NPIX];            // 16 MB   [b][c][n]
__device__ float g_Kp[NB * CQK * NPIX];           // 16 MB   [b][c][n]
__device__ float g_V[NB * COUT * NPIX];           // 32 MB   [b][o][n]
__device__ float g_S[67108864];                   // 256 MB  [b][n][m]  (sim / attn, in-place softmax)

// ---------------------------------------------------------------------------
// Generic tiled fp32 GEMM.
//   C[row, col] = scale * sum_k A(k,row) * B(k,col) + bias[row]
//
// AMODE 0: A stored [M, K] row-major (k contiguous)   -> transpose-load
// AMODE 1: A stored [K, M] row-major (m contiguous)   -> direct-load
// BMODE 0: B stored [K, N] row-major (n contiguous)   -> direct-load
// BMODE 1: B stored [N, K] row-major (k contiguous)   -> transpose-load
//
// All dims must be multiples of the tile sizes (they are: 256/512/4096 vs 128,
// and K in {256,512,4096} vs 8).
// ---------------------------------------------------------------------------
template<int AMODE, int BMODE>
__global__ void __launch_bounds__(NTHREADS)
gemm_kernel(const float* __restrict__ A, int lda, size_t sA,
            const float* __restrict__ B, int ldb, size_t sB,
            float* __restrict__ C, int ldc, size_t sC,
            int K, const float* __restrict__ bias, float scale)
{
    __shared__ float As[BK * SLDA];
    __shared__ float Bs[BK * SLDA];

    const int t    = threadIdx.x;
    const int row0 = blockIdx.y * BM;
    const int col0 = blockIdx.x * BN;

    A += (size_t)blockIdx.z * sA;
    B += (size_t)blockIdx.z * sB;
    C += (size_t)blockIdx.z * sC;

    const int tx = t & 15;       // 0..15  (col frag)
    const int ty = t >> 4;       // 0..15  (row frag)

    // transpose-load indices: 128 rows x 8 k, one float4 per thread
    const int lr  = t >> 1;          // 0..127
    const int lkq = (t & 1) * 4;     // 0 or 4
    // direct-load indices: 8 k-rows x 128 cols, one float4 per thread
    const int dk = t >> 5;           // 0..7
    const int dc = (t & 31) * 4;     // 0..124

    float acc[8][8];
    #pragma unroll
    for (int i = 0; i < 8; i++)
        #pragma unroll
        for (int j = 0; j < 8; j++) acc[i][j] = 0.f;

    for (int k0 = 0; k0 < K; k0 += BK) {
        // ---- load A tile into As[k][m] ----
        if (AMODE == 0) {
            float4 v = *(const float4*)&A[(size_t)(row0 + lr) * lda + k0 + lkq];
            As[(lkq + 0) * SLDA + lr] = v.x;
            As[(lkq + 1) * SLDA + lr] = v.y;
            As[(lkq + 2) * SLDA + lr] = v.z;
            As[(lkq + 3) * SLDA + lr] = v.w;
        } else {
            float4 v = *(const float4*)&A[(size_t)(k0 + dk) * lda + row0 + dc];
            *(float4*)&As[dk * SLDA + dc] = v;
        }
        // ---- load B tile into Bs[k][n] ----
        if (BMODE == 0) {
            float4 v = *(const float4*)&B[(size_t)(k0 + dk) * ldb + col0 + dc];
            *(float4*)&Bs[dk * SLDA + dc] = v;
        } else {
            float4 v = *(const float4*)&B[(size_t)(col0 + lr) * ldb + k0 + lkq];
            Bs[(lkq + 0) * SLDA + lr] = v.x;
            Bs[(lkq + 1) * SLDA + lr] = v.y;
            Bs[(lkq + 2) * SLDA + lr] = v.z;
            Bs[(lkq + 3) * SLDA + lr] = v.w;
        }
        __syncthreads();

        #pragma unroll
        for (int kk = 0; kk < BK; kk++) {
            float4 a0 = *(float4*)&As[kk * SLDA + ty * 4];
            float4 a1 = *(float4*)&As[kk * SLDA + 64 + ty * 4];
            float4 b0 = *(float4*)&Bs[kk * SLDA + tx * 4];
            float4 b1 = *(float4*)&Bs[kk * SLDA + 64 + tx * 4];
            float a[8] = {a0.x, a0.y, a0.z, a0.w, a1.x, a1.y, a1.z, a1.w};
            float b[8] = {b0.x, b0.y, b0.z, b0.w, b1.x, b1.y, b1.z, b1.w};
            #pragma unroll
            for (int i = 0; i < 8; i++)
                #pragma unroll
                for (int j = 0; j < 8; j++)
                    acc[i][j] = fmaf(a[i], b[j], acc[i][j]);
        }
        __syncthreads();
    }

    // ---- epilogue: scale, bias, float4 stores ----
    #pragma unroll
    for (int i = 0; i < 8; i++) {
        int rloc = (i < 4) ? (ty * 4 + i) : (64 + ty * 4 + (i - 4));
        int rm = row0 + rloc;
        float bval = (bias != nullptr) ? bias[rm] : 0.f;
        #pragma unroll
        for (int jh = 0; jh < 2; jh++) {
            float4 o;
            o.x = acc[i][jh * 4 + 0] * scale + bval;
            o.y = acc[i][jh * 4 + 1] * scale + bval;
            o.z = acc[i][jh * 4 + 2] * scale + bval;
            o.w = acc[i][jh * 4 + 3] * scale + bval;
            int cn = col0 + jh * 64 + tx * 4;
            *(float4*)&C[(size_t)rm * ldc + cn] = o;
        }
    }
}

// ---------------------------------------------------------------------------
// Row softmax over the materialized sim matrix: 16384 rows of 4096 fp32,
// one block per row, 16 elems/thread in registers.
// ---------------------------------------------------------------------------
__global__ void __launch_bounds__(256)
softmax_kernel(float* __restrict__ S)
{
    float* row = S + (size_t)blockIdx.x * NPIX;
    const int t = threadIdx.x;

    float v[16];
    float m = -1e30f;
    #pragma unroll
    for (int i = 0; i < 16; i++) {
        v[i] = row[t + i * 256];
        m = fmaxf(m, v[i]);
    }
    #pragma unroll
    for (int o = 16; o > 0; o >>= 1)
        m = fmaxf(m, __shfl_xor_sync(0xffffffffu, m, o));

    __shared__ float smax[8];
    __shared__ float ssum[8];
    if ((t & 31) == 0) smax[t >> 5] = m;
    __syncthreads();
    float mm = smax[0];
    #pragma unroll
    for (int i = 1; i < 8; i++) mm = fmaxf(mm, smax[i]);

    float s = 0.f;
    #pragma unroll
    for (int i = 0; i < 16; i++) {
        v[i] = __expf(v[i] - mm);
        s += v[i];
    }
    #pragma unroll
    for (int o = 16; o > 0; o >>= 1)
        s += __shfl_xor_sync(0xffffffffu, s, o);
    if ((t & 31) == 0) ssum[t >> 5] = s;
    __syncthreads();
    float tot = 0.f;
    #pragma unroll
    for (int i = 0; i < 8; i++) tot += ssum[i];
    float inv = 1.0f / tot;

    #pragma unroll
    for (int i = 0; i < 16; i++)
        row[t + i * 256] = v[i] * inv;
}

// ---------------------------------------------------------------------------
// Launch: QKV projections -> sim = Q^T K * c^-0.5 -> softmax -> out = attn @ V
// Input order (metadata): query_feats, key_feats, Wq, bq, Wk, bk, Wv, bv
// Output: [B, C_OUT, H, W] fp32
// ---------------------------------------------------------------------------
extern "C" void kernel_launch(void* const* d_in, const int* in_sizes, int n_in,
                              void* d_out, int out_size)
{
    const float* qfeat = (const float*)d_in[0];   // [4,512,4096]
    const float* kfeat = (const float*)d_in[1];   // [4,512,4096]
    const float* Wq    = (const float*)d_in[2];   // [256,512]
    const float* bq    = (const float*)d_in[3];   // [256]
    const float* Wk    = (const float*)d_in[4];   // [256,512]
    const float* bk    = (const float*)d_in[5];   // [256]
    const float* Wv    = (const float*)d_in[6];   // [512,512]
    const float* bv    = (const float*)d_in[7];   // [512]
    float* out = (float*)d_out;

    float *Qd, *Kd, *Vd, *Sd;
    cudaGetSymbolAddress((void**)&Qd, g_Q);
    cudaGetSymbolAddress((void**)&Kd, g_Kp);
    cudaGetSymbolAddress((void**)&Vd, g_V);
    cudaGetSymbolAddress((void**)&Sd, g_S);

    const dim3 blk(NTHREADS);

    // 1) Q = Wq @ qfeat + bq          [b][256][4096]
    gemm_kernel<0, 0><<<dim3(NPIX / BN, CQK / BM, NB), blk>>>(
        Wq, CIN, (size_t)0,
        qfeat, NPIX, (size_t)CIN * NPIX,
        Qd, NPIX, (size_t)CQK * NPIX,
        CIN, bq, 1.0f);

    // 2) K = Wk @ kfeat + bk          [b][256][4096]
    gemm_kernel<0, 0><<<dim3(NPIX / BN, CQK / BM, NB), blk>>>(
        Wk, CIN, (size_t)0,
        kfeat, NPIX, (size_t)CIN * NPIX,
        Kd, NPIX, (size_t)CQK * NPIX,
        CIN, bk, 1.0f);

    // 3) V = Wv @ kfeat + bv          [b][512][4096]
    gemm_kernel<0, 0><<<dim3(NPIX / BN, COUT / BM, NB), blk>>>(
        Wv, CIN, (size_t)0,
        kfeat, NPIX, (size_t)CIN * NPIX,
        Vd, NPIX, (size_t)COUT * NPIX,
        CIN, bv, 1.0f);

    // 4) sim[n,m] = (1/16) * sum_c Q[c,n] K[c,m]      [b][4096][4096]
    gemm_kernel<1, 0><<<dim3(NPIX / BN, NPIX / BM, NB), blk>>>(
        Qd, NPIX, (size_t)CQK * NPIX,
        Kd, NPIX, (size_t)CQK * NPIX,
        Sd, NPIX, (size_t)NPIX * NPIX,
        CQK, nullptr, 0.0625f);

    // 5) softmax over last dim (in place)
    softmax_kernel<<<NB * NPIX, 256>>>(Sd);

    // 6) out[b][o][n] = sum_m V[o,m] * attn[n,m]
    gemm_kernel<0, 1><<<dim3(NPIX / BN, COUT / BM, NB), blk>>>(
        Vd, NPIX, (size_t)COUT * NPIX,
        Sd, NPIX, (size_t)NPIX * NPIX,
        out, NPIX, (size_t)COUT * NPIX,
        NPIX, nullptr, 1.0f);
}

// round 2
// speedup vs baseline: 1.0014x; 1.0014x over previous
#include <cuda_runtime.h>
#include <cstddef>

// Problem constants
//  B=4, C_IN=512, H=W=64 -> N=4096, C_QK=256, C_OUT=512
#define NB    4
#define CIN   512
#define NPIX  4096
#define CQK   256
#define COUT  512

// GEMM tiling
#define BM 128
#define BN 128
#define BK 8
#define SLDA 132          // padded smem row stride (floats); 132%32=4 -> conflict-free transpose stores
#define NTHREADS 256

// ---------------------------------------------------------------------------
// Scratch (device globals; no runtime allocation allowed)
// ---------------------------------------------------------------------------
__device__ float g_Q[NB * CQK * NPIX];            // 16 MB   [b][c][n]
__device__ float g_Kp[NB * CQK * NPIX];           // 16 MB   [b][c][n]
__device__ float g_V[NB * COUT * NPIX];           // 32 MB   [b][o][n]
__device__ float g_S[67108864];                   // 256 MB  [b][n][m]  (sim / attn, in-place softmax)

// ---------------------------------------------------------------------------
// Generic tiled fp32 GEMM.
//   C[row, col] = scale * sum_k A(k,row) * B(k,col) + bias[row]
//
// AMODE 0: A stored [M, K] row-major (k contiguous)   -> transpose-load
// AMODE 1: A stored [K, M] row-major (m contiguous)   -> direct-load
// BMODE 0: B stored [K, N] row-major (n contiguous)   -> direct-load
// BMODE 1: B stored [N, K] row-major (k contiguous)   -> transpose-load
//
// All dims must be multiples of the tile sizes (they are: 256/512/4096 vs 128,
// and K in {256,512,4096} vs 8).
// ---------------------------------------------------------------------------
template<int AMODE, int BMODE>
__global__ void __launch_bounds__(NTHREADS)
gemm_kernel(const float* __restrict__ A, int lda, size_t sA,
            const float* __restrict__ B, int ldb, size_t sB,
            float* __restrict__ C, int ldc, size_t sC,
            int K, const float* __restrict__ bias, float scale)
{
    __shared__ float As[BK * SLDA];
    __shared__ float Bs[BK * SLDA];

    const int t    = threadIdx.x;
    const int row0 = blockIdx.y * BM;
    const int col0 = blockIdx.x * BN;

    A += (size_t)blockIdx.z * sA;
    B += (size_t)blockIdx.z * sB;
    C += (size_t)blockIdx.z * sC;

    const int tx = t & 15;       // 0..15  (col frag)
    const int ty = t >> 4;       // 0..15  (row frag)

    // transpose-load indices: 128 rows x 8 k, one float4 per thread
    const int lr  = t >> 1;          // 0..127
    const int lkq = (t & 1) * 4;     // 0 or 4
    // direct-load indices: 8 k-rows x 128 cols, one float4 per thread
    const int dk = t >> 5;           // 0..7
    const int dc = (t & 31) * 4;     // 0..124

    float acc[8][8];
    #pragma unroll
    for (int i = 0; i < 8; i++)
        #pragma unroll
        for (int j = 0; j < 8; j++) acc[i][j] = 0.f;

    for (int k0 = 0; k0 < K; k0 += BK) {
        // ---- load A tile into As[k][m] ----
        if (AMODE == 0) {
            float4 v = *(const float4*)&A[(size_t)(row0 + lr) * lda + k0 + lkq];
            As[(lkq + 0) * SLDA + lr] = v.x;
            As[(lkq + 1) * SLDA + lr] = v.y;
            As[(lkq + 2) * SLDA + lr] = v.z;
            As[(lkq + 3) * SLDA + lr] = v.w;
        } else {
            float4 v = *(const float4*)&A[(size_t)(k0 + dk) * lda + row0 + dc];
            *(float4*)&As[dk * SLDA + dc] = v;
        }
        // ---- load B tile into Bs[k][n] ----
        if (BMODE == 0) {
            float4 v = *(const float4*)&B[(size_t)(k0 + dk) * ldb + col0 + dc];
            *(float4*)&Bs[dk * SLDA + dc] = v;
        } else {
            float4 v = *(const float4*)&B[(size_t)(col0 + lr) * ldb + k0 + lkq];
            Bs[(lkq + 0) * SLDA + lr] = v.x;
            Bs[(lkq + 1) * SLDA + lr] = v.y;
            Bs[(lkq + 2) * SLDA + lr] = v.z;
            Bs[(lkq + 3) * SLDA + lr] = v.w;
        }
        __syncthreads();

        #pragma unroll
        for (int kk = 0; kk < BK; kk++) {
            float4 a0 = *(float4*)&As[kk * SLDA + ty * 4];
            float4 a1 = *(float4*)&As[kk * SLDA + 64 + ty * 4];
            float4 b0 = *(float4*)&Bs[kk * SLDA + tx * 4];
            float4 b1 = *(float4*)&Bs[kk * SLDA + 64 + tx * 4];
            float a[8] = {a0.x, a0.y, a0.z, a0.w, a1.x, a1.y, a1.z, a1.w};
            float b[8] = {b0.x, b0.y, b0.z, b0.w, b1.x, b1.y, b1.z, b1.w};
            #pragma unroll
            for (int i = 0; i < 8; i++)
                #pragma unroll
                for (int j = 0; j < 8; j++)
                    acc[i][j] = fmaf(a[i], b[j], acc[i][j]);
        }
        __syncthreads();
    }

    // ---- epilogue: scale, bias, float4 stores ----
    #pragma unroll
    for (int i = 0; i < 8; i++) {
        int rloc = (i < 4) ? (ty * 4 + i) : (64 + ty * 4 + (i - 4));
        int rm = row0 + rloc;
        float bval = (bias != nullptr) ? bias[rm] : 0.f;
        #pragma unroll
        for (int jh = 0; jh < 2; jh++) {
            float4 o;
            o.x = acc[i][jh * 4 + 0] * scale + bval;
            o.y = acc[i][jh * 4 + 1] * scale + bval;
            o.z = acc[i][jh * 4 + 2] * scale + bval;
            o.w = acc[i][jh * 4 + 3] * scale + bval;
            int cn = col0 + jh * 64 + tx * 4;
            *(float4*)&C[(size_t)rm * ldc + cn] = o;
        }
    }
}

// ---------------------------------------------------------------------------
// Row softmax over the materialized sim matrix: 16384 rows of 4096 fp32,
// one block per row, 16 elems/thread in registers.
// ---------------------------------------------------------------------------
__global__ void __launch_bounds__(256)
softmax_kernel(float* __restrict__ S)
{
    float* row = S + (size_t)blockIdx.x * NPIX;
    const int t = threadIdx.x;

    float v[16];
    float m = -1e30f;
    #pragma unroll
    for (int i = 0; i < 16; i++) {
        v[i] = row[t + i * 256];
        m = fmaxf(m, v[i]);
    }
    #pragma unroll
    for (int o = 16; o > 0; o >>= 1)
        m = fmaxf(m, __shfl_xor_sync(0xffffffffu, m, o));

    __shared__ float smax[8];
    __shared__ float ssum[8];
    if ((t & 31) == 0) smax[t >> 5] = m;
    __syncthreads();
    float mm = smax[0];
    #pragma unroll
    for (int i = 1; i < 8; i++) mm = fmaxf(mm, smax[i]);

    float s = 0.f;
    #pragma unroll
    for (int i = 0; i < 16; i++) {
        v[i] = __expf(v[i] - mm);
        s += v[i];
    }
    #pragma unroll
    for (int o = 16; o > 0; o >>= 1)
        s += __shfl_xor_sync(0xffffffffu, s, o);
    if ((t & 31) == 0) ssum[t >> 5] = s;
    __syncthreads();
    float tot = 0.f;
    #pragma unroll
    for (int i = 0; i < 8; i++) tot += ssum[i];
    float inv = 1.0f / tot;

    #pragma unroll
    for (int i = 0; i < 16; i++)
        row[t + i * 256] = v[i] * inv;
}

// ---------------------------------------------------------------------------
// Launch: QKV projections -> sim = Q^T K * c^-0.5 -> softmax -> out = attn @ V
// Input order (metadata): query_feats, key_feats, Wq, bq, Wk, bk, Wv, bv
// Output: [B, C_OUT, H, W] fp32
// ---------------------------------------------------------------------------
extern "C" void kernel_launch(void* const* d_in, const int* in_sizes, int n_in,
                              void* d_out, int out_size)
{
    const float* qfeat = (const float*)d_in[0];   // [4,512,4096]
    const float* kfeat = (const float*)d_in[1];   // [4,512,4096]
    const float* Wq    = (const float*)d_in[2];   // [256,512]
    const float* bq    = (const float*)d_in[3];   // [256]
    const float* Wk    = (const float*)d_in[4];   // [256,512]
    const float* bk    = (const float*)d_in[5];   // [256]
    const float* Wv    = (const float*)d_in[6];   // [512,512]
    const float* bv    = (const float*)d_in[7];   // [512]
    float* out = (float*)d_out;

    float *Qd, *Kd, *Vd, *Sd;
    cudaGetSymbolAddress((void**)&Qd, g_Q);
    cudaGetSymbolAddress((void**)&Kd, g_Kp);
    cudaGetSymbolAddress((void**)&Vd, g_V);
    cudaGetSymbolAddress((void**)&Sd, g_S);

    const dim3 blk(NTHREADS);

    // 1) Q = Wq @ qfeat + bq          [b][256][4096]
    gemm_kernel<0, 0><<<dim3(NPIX / BN, CQK / BM, NB), blk>>>(
        Wq, CIN, (size_t)0,
        qfeat, NPIX, (size_t)CIN * NPIX,
        Qd, NPIX, (size_t)CQK * NPIX,
        CIN, bq, 1.0f);

    // 2) K = Wk @ kfeat + bk          [b][256][4096]
    gemm_kernel<0, 0><<<dim3(NPIX / BN, CQK / BM, NB), blk>>>(
        Wk, CIN, (size_t)0,
        kfeat, NPIX, (size_t)CIN * NPIX,
        Kd, NPIX, (size_t)CQK * NPIX,
        CIN, bk, 1.0f);

    // 3) V = Wv @ kfeat + bv          [b][512][4096]
    gemm_kernel<0, 0><<<dim3(NPIX / BN, COUT / BM, NB), blk>>>(
        Wv, CIN, (size_t)0,
        kfeat, NPIX, (size_t)CIN * NPIX,
        Vd, NPIX, (size_t)COUT * NPIX,
        CIN, bv, 1.0f);

    // 4) sim[n,m] = (1/16) * sum_c Q[c,n] K[c,m]      [b][4096][4096]
    gemm_kernel<1, 0><<<dim3(NPIX / BN, NPIX / BM, NB), blk>>>(
        Qd, NPIX, (size_t)CQK * NPIX,
        Kd, NPIX, (size_t)CQK * NPIX,
        Sd, NPIX, (size_t)NPIX * NPIX,
        CQK, nullptr, 0.0625f);

    // 5) softmax over last dim (in place)
    softmax_kernel<<<NB * NPIX, 256>>>(Sd);

    // 6) out[b][o][n] = sum_m V[o,m] * attn[n,m]
    gemm_kernel<0, 1><<<dim3(NPIX / BN, COUT / BM, NB), blk>>>(
        Vd, NPIX, (size_t)COUT * NPIX,
        Sd, NPIX, (size_t)NPIX * NPIX,
        out, NPIX, (size_t)COUT * NPIX,
        NPIX, nullptr, 1.0f);
}

// round 5
// speedup vs baseline: 1.9024x; 1.8998x over previous
#include <cuda_runtime.h>
#include <cuda_bf16.h>
#include <cstdint>
#include <cstddef>

#define NB    4
#define CIN   512
#define NPIX  4096
#define CQK   256
#define COUT  512

// GEMM tiling: block 128x128, K-chunk 32 bf16, 3-stage cp.async pipeline
#define ROWB    80            // padded smem row bytes (64B data + 16B pad, conflict-free)
#define STAGE_SZ (128*ROWB*2) // A + B tile per stage = 20480 B
#define NSTAGE  3
#define GSMEM   (STAGE_SZ*NSTAGE)

// -------------------- scratch (device globals; no runtime alloc) ----------
// Concatenated K layouts: A-side = [hi|hi|lo], B-side = [hi|lo|hi]
__device__ __nv_bfloat16 g_XqA[(size_t)NB*NPIX*3*CIN];   // Xq^T A-order
__device__ __nv_bfloat16 g_XkA[(size_t)NB*NPIX*3*CIN];   // Xk^T A-order (K proj)
__device__ __nv_bfloat16 g_XkB[(size_t)NB*NPIX*3*CIN];   // Xk^T B-order (V proj)
__device__ __nv_bfloat16 g_Wq3[CQK*3*CIN];               // B-order
__device__ __nv_bfloat16 g_Wk3[CQK*3*CIN];               // B-order
__device__ __nv_bfloat16 g_Wv3[COUT*3*CIN];              // A-order
__device__ __nv_bfloat16 g_Q3[(size_t)NB*NPIX*3*CQK];    // A-order [b][n][3*256]
__device__ __nv_bfloat16 g_K3[(size_t)NB*NPIX*3*CQK];    // B-order
__device__ __nv_bfloat16 g_V3[(size_t)NB*COUT*3*NPIX];   // A-order [b][o][3*4096]
__device__ float         g_S [(size_t)NB*NPIX*NPIX];     // fp32 sim
__device__ __nv_bfloat16 g_A3[(size_t)NB*NPIX*3*NPIX];   // attn B-order

// -------------------- PTX helpers (all baseline sm_80+) -------------------
__device__ __forceinline__ uint32_t s2u(const void* p) {
    uint32_t a;
    asm("{ .reg .u64 t; cvta.to.shared.u64 t, %1; cvt.u32.u64 %0, t; }" : "=r"(a) : "l"(p));
    return a;
}
__device__ __forceinline__ void cp16(uint32_t s, const void* g) {
    asm volatile("cp.async.cg.shared.global [%0], [%1], 16;" :: "r"(s), "l"(g));
}
#define CP_COMMIT() asm volatile("cp.async.commit_group;" ::: "memory")
#define CP_WAIT1()  asm volatile("cp.async.wait_group 1;" ::: "memory")

__device__ __forceinline__ void ldm4(uint32_t& r0, uint32_t& r1, uint32_t& r2, uint32_t& r3,
                                     uint32_t a) {
    asm volatile("ldmatrix.sync.aligned.m8n8.x4.shared.b16 {%0,%1,%2,%3}, [%4];"
                 : "=r"(r0), "=r"(r1), "=r"(r2), "=r"(r3) : "r"(a));
}
__device__ __forceinline__ void mma16816(float* d, const uint32_t* a, uint32_t b0, uint32_t b1) {
    asm volatile(
      "mma.sync.aligned.m16n8k16.row.col.f32.bf16.bf16.f32 "
      "{%0,%1,%2,%3},{%4,%5,%6,%7},{%8,%9},{%0,%1,%2,%3};"
      : "+f"(d[0]), "+f"(d[1]), "+f"(d[2]), "+f"(d[3])
      : "r"(a[0]), "r"(a[1]), "r"(a[2]), "r"(a[3]), "r"(b0), "r"(b1));
}

// -------------------- canonical bf16 HMMA GEMM ----------------------------
// D[M,N] = scale * (A[M,Kp] . B[N,Kp]^T) + bias_row[m] + bias_col[n]
// EPI 0: fp32 out.  EPI 1: bf16 concat out (hi at +0 and +offH1, lo at +offL).
template<int EPI>
__global__ void __launch_bounds__(256)
gemm_bf16(const __nv_bfloat16* __restrict__ A, size_t sA,
          const __nv_bfloat16* __restrict__ B, size_t sB,
          int Kp,
          float* __restrict__ Cf, __nv_bfloat16* __restrict__ C3,
          size_t ldc, size_t sC, size_t offH1, size_t offL,
          const float* __restrict__ bias_row, const float* __restrict__ bias_col,
          float scale)
{
    extern __shared__ __align__(128) char smem[];
    const uint32_t sb = s2u(smem);
    const int tid = threadIdx.x, lane = tid & 31, wid = tid >> 5;
    const int wm0 = (wid >> 2) * 64;     // warp M origin (0 or 64)
    const int wn0 = (wid & 3) * 32;      // warp N origin
    const int m0 = blockIdx.y * 128, n0 = blockIdx.x * 128, z = blockIdx.z;

    A += (size_t)z * sA + (size_t)m0 * Kp;
    B += (size_t)z * sB + (size_t)n0 * Kp;

    const int r0 = tid >> 2;         // 0..63 (this thread loads rows r0 and r0+64)
    const int c0 = tid & 3;          // 16B chunk within 64B row

    const int nk = Kp / 32;

    // stage loader: A tile then B tile; 4 cp.async of 16B per thread
    auto load_stage = [&](int st, int kc) {
        const __nv_bfloat16* ga = A + (size_t)kc * 32;
        const __nv_bfloat16* gb = B + (size_t)kc * 32;
        uint32_t sa = sb + st * STAGE_SZ;
        uint32_t sbm = sa + 128 * ROWB;
        cp16(sa  + r0 * ROWB + c0 * 16,        ga + (size_t)r0 * Kp + c0 * 8);
        cp16(sa  + (r0 + 64) * ROWB + c0 * 16, ga + (size_t)(r0 + 64) * Kp + c0 * 8);
        cp16(sbm + r0 * ROWB + c0 * 16,        gb + (size_t)r0 * Kp + c0 * 8);
        cp16(sbm + (r0 + 64) * ROWB + c0 * 16, gb + (size_t)(r0 + 64) * Kp + c0 * 8);
    };

    float acc[4][4][4];
    #pragma unroll
    for (int i = 0; i < 4; i++)
        #pragma unroll
        for (int j = 0; j < 4; j++)
            #pragma unroll
            for (int q = 0; q < 4; q++) acc[i][j][q] = 0.f;

    load_stage(0, 0); CP_COMMIT();
    load_stage(1, 1); CP_COMMIT();

    // lane-invariant parts of ldmatrix addresses
    const int arow = wm0 + (lane & 15);
    const int acsel = (lane >> 4);            // 0/1 -> k chunk select
    const int brow = wn0 + (lane & 7) + ((lane >> 4) & 1) * 8;
    const int bcsel = (lane >> 3) & 1;

    for (int k = 0; k < nk; k++) {
        CP_WAIT1();
        __syncthreads();
        if (k + 2 < nk) load_stage((k + 2) % NSTAGE, k + 2);
        CP_COMMIT();

        const uint32_t sa = sb + (k % NSTAGE) * STAGE_SZ;
        const uint32_t sbm = sa + 128 * ROWB;

        #pragma unroll
        for (int ks = 0; ks < 2; ks++) {
            uint32_t a[4][4], bfr[2][4];
            const uint32_t ac = (ks * 2 + acsel) * 16;
            #pragma unroll
            for (int i = 0; i < 4; i++)
                ldm4(a[i][0], a[i][1], a[i][2], a[i][3],
                     sa + (arow + i * 16) * ROWB + ac);
            const uint32_t bc = (ks * 2 + bcsel) * 16;
            #pragma unroll
            for (int j = 0; j < 2; j++)
                ldm4(bfr[j][0], bfr[j][1], bfr[j][2], bfr[j][3],
                     sbm + (brow + j * 16) * ROWB + bc);
            #pragma unroll
            for (int i = 0; i < 4; i++)
                #pragma unroll
                for (int jn = 0; jn < 4; jn++)
                    mma16816(acc[i][jn], a[i],
                             bfr[jn >> 1][(jn & 1) * 2], bfr[jn >> 1][(jn & 1) * 2 + 1]);
        }
        __syncthreads();
    }

    // -------- epilogue --------
    const int mb = m0 + wm0 + (lane >> 2);
    const int nb = n0 + wn0 + (lane & 3) * 2;
    #pragma unroll
    for (int i = 0; i < 4; i++) {
        #pragma unroll
        for (int half = 0; half < 2; half++) {      // d0,d1 vs d2,d3 (row +8)
            const int m = mb + i * 16 + half * 8;
            const float br = bias_row ? bias_row[m] : 0.f;
            #pragma unroll
            for (int jn = 0; jn < 4; jn++) {
                const int n = nb + jn * 8;
                float v0 = acc[i][jn][half * 2 + 0] * scale + br;
                float v1 = acc[i][jn][half * 2 + 1] * scale + br;
                if (bias_col) { v0 += bias_col[n]; v1 += bias_col[n + 1]; }
                if (EPI == 0) {
                    float2 o = make_float2(v0, v1);
                    *(float2*)&Cf[(size_t)z * sC + (size_t)m * ldc + n] = o;
                } else {
                    __nv_bfloat16 h0 = __float2bfloat16(v0);
                    __nv_bfloat16 h1 = __float2bfloat16(v1);
                    __nv_bfloat162 hp; hp.x = h0; hp.y = h1;
                    __nv_bfloat162 lp;
                    lp.x = __float2bfloat16(v0 - __bfloat162float(h0));
                    lp.y = __float2bfloat16(v1 - __bfloat162float(h1));
                    __nv_bfloat16* base = C3 + (size_t)z * sC + (size_t)m * ldc;
                    *(__nv_bfloat162*)&base[n] = hp;
                    *(__nv_bfloat162*)&base[offH1 + n] = hp;
                    *(__nv_bfloat162*)&base[offL + n] = lp;
                }
            }
        }
    }
}

// ------------- transpose + split -> concat layouts ------------------------
// X[b][CIN][NPIX] fp32 -> XA [b][NPIX][3*CIN] (hi|hi|lo), XB optional (hi|lo|hi)
__global__ void __launch_bounds__(256)
transpose_split3(const float* __restrict__ X,
                 __nv_bfloat16* __restrict__ XA, __nv_bfloat16* __restrict__ XB)
{
    __shared__ float t[32][33];
    const int b = blockIdx.z, n0 = blockIdx.x * 32, c0 = blockIdx.y * 32;
    const int tx = threadIdx.x & 31, ty = threadIdx.x >> 5;
    const float* Xb = X + (size_t)b * CIN * NPIX;
    #pragma unroll
    for (int r = 0; r < 4; r++)
        t[ty + r * 8][tx] = Xb[(size_t)(c0 + ty + r * 8) * NPIX + n0 + tx];
    __syncthreads();
    const size_t ob = (size_t)b * NPIX * 3 * CIN;
    #pragma unroll
    for (int r = 0; r < 4; r++) {
        const int n = n0 + ty + r * 8;
        const int c = c0 + tx;
        float v = t[tx][ty + r * 8];
        __nv_bfloat16 h = __float2bfloat16(v);
        __nv_bfloat16 l = __float2bfloat16(v - __bfloat162float(h));
        const size_t row = ob + (size_t)n * (3 * CIN);
        XA[row + c] = h; XA[row + CIN + c] = h; XA[row + 2 * CIN + c] = l;
        if (XB) { XB[row + c] = h; XB[row + CIN + c] = l; XB[row + 2 * CIN + c] = h; }
    }
}

// Weight split: W[o][CIN] -> W3[o][3*CIN]; order 0 = A (hi|hi|lo), 1 = B (hi|lo|hi)
__global__ void wsplit3(const float* __restrict__ W, __nv_bfloat16* __restrict__ W3,
                        int total, int order)
{
    int i = blockIdx.x * 256 + threadIdx.x;
    if (i >= total) return;
    const int o = i / CIN, c = i % CIN;
    float v = W[i];
    __nv_bfloat16 h = __float2bfloat16(v);
    __nv_bfloat16 l = __float2bfloat16(v - __bfloat162float(h));
    __nv_bfloat16* row = W3 + (size_t)o * (3 * CIN);
    row[c] = h;
    row[CIN + c] = order ? l : h;
    row[2 * CIN + c] = order ? h : l;
}

// ------------- softmax: fp32 S rows -> attn concat B-order ----------------
__global__ void __launch_bounds__(256)
softmax3(const float* __restrict__ S, __nv_bfloat16* __restrict__ A3)
{
    const size_t rb = (size_t)blockIdx.x * NPIX;
    const float* row = S + rb;
    __nv_bfloat16* orow = A3 + (size_t)blockIdx.x * (3 * NPIX);
    const int t = threadIdx.x;
    float v[16];
    float m = -1e30f;
    #pragma unroll
    for (int i = 0; i < 16; i++) { v[i] = row[t + i * 256]; m = fmaxf(m, v[i]); }
    #pragma unroll
    for (int o = 16; o > 0; o >>= 1) m = fmaxf(m, __shfl_xor_sync(~0u, m, o));
    __shared__ float smax[8], ssum[8];
    if ((t & 31) == 0) smax[t >> 5] = m;
    __syncthreads();
    float mm = smax[0];
    #pragma unroll
    for (int i = 1; i < 8; i++) mm = fmaxf(mm, smax[i]);
    float s = 0.f;
    #pragma unroll
    for (int i = 0; i < 16; i++) { v[i] = __expf(v[i] - mm); s += v[i]; }
    #pragma unroll
    for (int o = 16; o > 0; o >>= 1) s += __shfl_xor_sync(~0u, s, o);
    if ((t & 31) == 0) ssum[t >> 5] = s;
    __syncthreads();
    float tot = 0.f;
    #pragma unroll
    for (int i = 0; i < 8; i++) tot += ssum[i];
    const float inv = 1.0f / tot;
    #pragma unroll
    for (int i = 0; i < 16; i++) {
        const int k = t + i * 256;
        float a = v[i] * inv;
        __nv_bfloat16 h = __float2bfloat16(a);
        __nv_bfloat16 l = __float2bfloat16(a - __bfloat162float(h));
        orow[k] = h;                 // seg0: hi
        orow[NPIX + k] = l;          // seg1: lo
        orow[2 * NPIX + k] = h;      // seg2: hi
    }
}

// ------------------------------- host -------------------------------------
extern "C" void kernel_launch(void* const* d_in, const int* in_sizes, int n_in,
                              void* d_out, int out_size)
{
    const float* qfeat = (const float*)d_in[0];
    const float* kfeat = (const float*)d_in[1];
    const float* Wq = (const float*)d_in[2];
    const float* bq = (const float*)d_in[3];
    const float* Wk = (const float*)d_in[4];
    const float* bk = (const float*)d_in[5];
    const float* Wv = (const float*)d_in[6];
    const float* bv = (const float*)d_in[7];
    float* out = (float*)d_out;

    void *XqA, *XkA, *XkB, *Wq3, *Wk3, *Wv3, *Q3, *K3, *V3, *Sd, *A3;
    cudaGetSymbolAddress(&XqA, g_XqA);
    cudaGetSymbolAddress(&XkA, g_XkA);
    cudaGetSymbolAddress(&XkB, g_XkB);
    cudaGetSymbolAddress(&Wq3, g_Wq3);
    cudaGetSymbolAddress(&Wk3, g_Wk3);
    cudaGetSymbolAddress(&Wv3, g_Wv3);
    cudaGetSymbolAddress(&Q3, g_Q3);
    cudaGetSymbolAddress(&K3, g_K3);
    cudaGetSymbolAddress(&V3, g_V3);
    cudaGetSymbolAddress(&Sd, g_S);
    cudaGetSymbolAddress(&A3, g_A3);

    cudaFuncSetAttribute(gemm_bf16<0>, cudaFuncAttributeMaxDynamicSharedMemorySize, GSMEM);
    cudaFuncSetAttribute(gemm_bf16<1>, cudaFuncAttributeMaxDynamicSharedMemorySize, GSMEM);

    // 0) prep
    wsplit3<<<(CQK * CIN + 255) / 256, 256>>>(Wq, (__nv_bfloat16*)Wq3, CQK * CIN, 1);
    wsplit3<<<(CQK * CIN + 255) / 256, 256>>>(Wk, (__nv_bfloat16*)Wk3, CQK * CIN, 1);
    wsplit3<<<(COUT * CIN + 255) / 256, 256>>>(Wv, (__nv_bfloat16*)Wv3, COUT * CIN, 0);
    transpose_split3<<<dim3(NPIX / 32, CIN / 32, NB), 256>>>(
        qfeat, (__nv_bfloat16*)XqA, nullptr);
    transpose_split3<<<dim3(NPIX / 32, CIN / 32, NB), 256>>>(
        kfeat, (__nv_bfloat16*)XkA, (__nv_bfloat16*)XkB);

    // 1) Q3[b][n][3*256] = XqA . Wq3^T + bq   (M=4096, N=256, Kp=1536) A-order out
    gemm_bf16<1><<<dim3(CQK / 128, NPIX / 128, NB), 256, GSMEM>>>(
        (const __nv_bfloat16*)XqA, (size_t)NPIX * 3 * CIN,
        (const __nv_bfloat16*)Wq3, 0, 3 * CIN,
        nullptr, (__nv_bfloat16*)Q3, (size_t)3 * CQK, (size_t)NPIX * 3 * CQK,
        CQK, 2 * CQK, nullptr, bq, 1.0f);

    // 2) K3 (B-order out)
    gemm_bf16<1><<<dim3(CQK / 128, NPIX / 128, NB), 256, GSMEM>>>(
        (const __nv_bfloat16*)XkA, (size_t)NPIX * 3 * CIN,
        (const __nv_bfloat16*)Wk3, 0, 3 * CIN,
        nullptr, (__nv_bfloat16*)K3, (size_t)3 * CQK, (size_t)NPIX * 3 * CQK,
        2 * CQK, CQK, nullptr, bk, 1.0f);

    // 3) V3[b][o][3*4096] = Wv3 . XkB^T + bv  (M=512, N=4096, Kp=1536) A-order out
    gemm_bf16<1><<<dim3(NPIX / 128, COUT / 128, NB), 256, GSMEM>>>(
        (const __nv_bfloat16*)Wv3, 0,
        (const __nv_bfloat16*)XkB, (size_t)NPIX * 3 * CIN, 3 * CIN,
        nullptr, (__nv_bfloat16*)V3, (size_t)3 * NPIX, (size_t)COUT * 3 * NPIX,
        NPIX, 2 * NPIX, bv, nullptr, 1.0f);

    // 4) S = (1/16) Q3 . K3^T   (M=N=4096, Kp=768) fp32 out
    gemm_bf16<0><<<dim3(NPIX / 128, NPIX / 128, NB), 256, GSMEM>>>(
        (const __nv_bfloat16*)Q3, (size_t)NPIX * 3 * CQK,
        (const __nv_bfloat16*)K3, (size_t)NPIX * 3 * CQK, 3 * CQK,
        (float*)Sd, nullptr, (size_t)NPIX, (size_t)NPIX * NPIX,
        0, 0, nullptr, nullptr, 0.0625f);

    // 5) softmax rows -> attn concat (B-order)
    softmax3<<<NB * NPIX, 256>>>((const float*)Sd, (__nv_bfloat16*)A3);

    // 6) out = V3 . A3^T   (M=512, N=4096, Kp=12288) fp32 out
    gemm_bf16<0><<<dim3(NPIX / 128, COUT / 128, NB), 256, GSMEM>>>(
        (const __nv_bfloat16*)V3, (size_t)COUT * 3 * NPIX,
        (const __nv_bfloat16*)A3, (size_t)NPIX * 3 * NPIX, 3 * NPIX,
        out, nullptr, (size_t)NPIX, (size_t)COUT * NPIX,
        0, 0, nullptr, nullptr, 1.0f);
}

// round 8
// speedup vs baseline: 2.5645x; 1.3481x over previous
#include <cuda_runtime.h>
#include <cstdint>
#include <cstddef>

#define NB    4
#define CIN   512
#define NPIX  4096
#define CQK   256
#define COUT  512

// GEMM tiling: block 128x128, K-chunk 64 int8 bytes, 3-stage cp.async pipeline
#define ROWB    80            // padded smem row bytes (64B data + 16B pad)
#define STAGE_SZ (128*ROWB*2)
#define NSTAGE  3
#define GSMEM   (STAGE_SZ*NSTAGE)
#define INV252  (1.0f/252.0f)

// -------------------- scratch (device globals) ----------------------------
// int8 K-concat: A-side [q1|q1|q2], B-side [q1|q2|q1]
__device__ int8_t g_XqA[(size_t)NB*NPIX*3*CIN];
__device__ int8_t g_XkA[(size_t)NB*NPIX*3*CIN];
__device__ int8_t g_XkB[(size_t)NB*NPIX*3*CIN];
__device__ int8_t g_Wq3[CQK*3*CIN];
__device__ int8_t g_Wk3[CQK*3*CIN];
__device__ int8_t g_Wv3[COUT*3*CIN];
__device__ float  g_Qf[(size_t)NB*NPIX*CQK];
__device__ float  g_Kf[(size_t)NB*NPIX*CQK];
__device__ float  g_Vf[(size_t)NB*COUT*NPIX];
__device__ int8_t g_Q3[(size_t)NB*NPIX*3*CQK];
__device__ int8_t g_K3[(size_t)NB*NPIX*3*CQK];
__device__ int8_t g_V3[(size_t)NB*COUT*3*NPIX];
__device__ float  g_S [(size_t)NB*NPIX*NPIX];
__device__ int8_t g_A3[(size_t)NB*NPIX*3*NPIX];
// scales (sigma = rowmax/127 ; x ~= sigma*(q1 + q2/252))
__device__ float g_sXq[NB*NPIX], g_sXk[NB*NPIX];
__device__ float g_sWq[CQK], g_sWk[CQK], g_sWv[COUT];
__device__ float g_sQ[NB*NPIX], g_sK[NB*NPIX], g_sV[NB*COUT], g_sAt[NB*NPIX];

// -------------------- PTX helpers -----------------------------------------
__device__ __forceinline__ uint32_t s2u(const void* p) {
    uint32_t a;
    asm("{ .reg .u64 t; cvta.to.shared.u64 t, %1; cvt.u32.u64 %0, t; }" : "=r"(a) : "l"(p));
    return a;
}
__device__ __forceinline__ void cp16(uint32_t s, const void* g) {
    asm volatile("cp.async.cg.shared.global [%0], [%1], 16;" :: "r"(s), "l"(g));
}
#define CP_COMMIT() asm volatile("cp.async.commit_group;" ::: "memory")
#define CP_WAIT1()  asm volatile("cp.async.wait_group 1;" ::: "memory")

__device__ __forceinline__ void ldm4(uint32_t& r0, uint32_t& r1, uint32_t& r2, uint32_t& r3,
                                     uint32_t a) {
    asm volatile("ldmatrix.sync.aligned.m8n8.x4.shared.b16 {%0,%1,%2,%3}, [%4];"
                 : "=r"(r0), "=r"(r1), "=r"(r2), "=r"(r3) : "r"(a));
}
__device__ __forceinline__ void mma16832(int* d, const uint32_t* a, uint32_t b0, uint32_t b1) {
    asm volatile(
      "mma.sync.aligned.m16n8k32.row.col.s32.s8.s8.s32 "
      "{%0,%1,%2,%3},{%4,%5,%6,%7},{%8,%9},{%0,%1,%2,%3};"
      : "+r"(d[0]), "+r"(d[1]), "+r"(d[2]), "+r"(d[3])
      : "r"(a[0]), "r"(a[1]), "r"(a[2]), "r"(a[3]), "r"(b0), "r"(b1));
}

// -------------------- canonical int8 Ozaki GEMM ---------------------------
// D[M,N] = scale * sigA[m]*sigB[n]*(acc0 + acc1/252) + bias_row[m] + bias_col[n]
// A: [M, Kp] int8 (Kp = 3K, segs [q1|q1|q2]); B: [N, Kp] (segs [q1|q2|q1]).
// Chunks (64B) with index < s0chunks accumulate into acc0, rest into acc1.
__global__ void __launch_bounds__(256)
gemm_s8(const int8_t* __restrict__ A, size_t sA,
        const int8_t* __restrict__ B, size_t sB,
        int Kp, int s0chunks,
        float* __restrict__ Cf, size_t ldc, size_t sC,
        const float* __restrict__ sAarr, size_t sAstr,
        const float* __restrict__ sBarr, size_t sBstr,
        const float* __restrict__ bias_row, const float* __restrict__ bias_col,
        float scale)
{
    extern __shared__ __align__(128) char smem[];
    const uint32_t sb = s2u(smem);
    const int tid = threadIdx.x, lane = tid & 31, wid = tid >> 5;
    const int wm0 = (wid >> 2) * 64;
    const int wn0 = (wid & 3) * 32;
    const int m0 = blockIdx.y * 128, n0 = blockIdx.x * 128, z = blockIdx.z;

    A += (size_t)z * sA + (size_t)m0 * Kp;
    B += (size_t)z * sB + (size_t)n0 * Kp;

    const int r0 = tid >> 2;
    const int c0 = tid & 3;
    const int nk = Kp / 64;

    auto load_stage = [&](int st, int kc) {
        const int8_t* ga = A + (size_t)kc * 64;
        const int8_t* gb = B + (size_t)kc * 64;
        uint32_t sa = sb + st * STAGE_SZ;
        uint32_t sbm = sa + 128 * ROWB;
        cp16(sa  + r0 * ROWB + c0 * 16,        ga + (size_t)r0 * Kp + c0 * 16);
        cp16(sa  + (r0 + 64) * ROWB + c0 * 16, ga + (size_t)(r0 + 64) * Kp + c0 * 16);
        cp16(sbm + r0 * ROWB + c0 * 16,        gb + (size_t)r0 * Kp + c0 * 16);
        cp16(sbm + (r0 + 64) * ROWB + c0 * 16, gb + (size_t)(r0 + 64) * Kp + c0 * 16);
    };

    int acc0[4][4][4], acc1[4][4][4];
    #pragma unroll
    for (int i = 0; i < 4; i++)
        #pragma unroll
        for (int j = 0; j < 4; j++)
            #pragma unroll
            for (int q = 0; q < 4; q++) { acc0[i][j][q] = 0; acc1[i][j][q] = 0; }

    load_stage(0, 0); CP_COMMIT();
    load_stage(1, 1); CP_COMMIT();

    const int arow = wm0 + (lane & 15);
    const int acsel = (lane >> 4);
    const int brow = wn0 + (lane & 7) + ((lane >> 4) & 1) * 8;
    const int bcsel = (lane >> 3) & 1;

    for (int k = 0; k < nk; k++) {
        CP_WAIT1();
        __syncthreads();
        if (k + 2 < nk) load_stage((k + 2) % NSTAGE, k + 2);
        CP_COMMIT();

        const uint32_t sa = sb + (k % NSTAGE) * STAGE_SZ;
        const uint32_t sbm = sa + 128 * ROWB;

        #pragma unroll
        for (int ks = 0; ks < 2; ks++) {
            uint32_t a[4][4], bfr[2][4];
            const uint32_t ac = (ks * 2 + acsel) * 16;
            #pragma unroll
            for (int i = 0; i < 4; i++)
                ldm4(a[i][0], a[i][1], a[i][2], a[i][3],
                     sa + (arow + i * 16) * ROWB + ac);
            const uint32_t bc = (ks * 2 + bcsel) * 16;
            #pragma unroll
            for (int j = 0; j < 2; j++)
                ldm4(bfr[j][0], bfr[j][1], bfr[j][2], bfr[j][3],
                     sbm + (brow + j * 16) * ROWB + bc);
            if (k < s0chunks) {
                #pragma unroll
                for (int i = 0; i < 4; i++)
                    #pragma unroll
                    for (int jn = 0; jn < 4; jn++)
                        mma16832(acc0[i][jn], a[i],
                                 bfr[jn >> 1][(jn & 1) * 2], bfr[jn >> 1][(jn & 1) * 2 + 1]);
            } else {
                #pragma unroll
                for (int i = 0; i < 4; i++)
                    #pragma unroll
                    for (int jn = 0; jn < 4; jn++)
                        mma16832(acc1[i][jn], a[i],
                                 bfr[jn >> 1][(jn & 1) * 2], bfr[jn >> 1][(jn & 1) * 2 + 1]);
            }
        }
        __syncthreads();
    }

    // -------- epilogue --------
    const int mb = m0 + wm0 + (lane >> 2);
    const int nb = n0 + wn0 + (lane & 3) * 2;
    #pragma unroll
    for (int i = 0; i < 4; i++) {
        #pragma unroll
        for (int half = 0; half < 2; half++) {
            const int m = mb + i * 16 + half * 8;
            const float sAm = sAarr[z * sAstr + m] * scale;
            const float br = bias_row ? bias_row[m] : 0.f;
            #pragma unroll
            for (int jn = 0; jn < 4; jn++) {
                const int n = nb + jn * 8;
                float f0 = (float)acc0[i][jn][half * 2 + 0]
                         + (float)acc1[i][jn][half * 2 + 0] * INV252;
                float f1 = (float)acc0[i][jn][half * 2 + 1]
                         + (float)acc1[i][jn][half * 2 + 1] * INV252;
                float v0 = f0 * sAm * sBarr[z * sBstr + n] + br;
                float v1 = f1 * sAm * sBarr[z * sBstr + n + 1] + br;
                if (bias_col) { v0 += bias_col[n]; v1 += bias_col[n + 1]; }
                *(float2*)&Cf[(size_t)z * sC + (size_t)m * ldc + n] = make_float2(v0, v1);
            }
        }
    }
}

// -------------------- quantization helpers --------------------------------
__device__ __forceinline__ float clamp127(float q) {
    return fminf(127.f, fmaxf(-127.f, q));
}

// Row-wise 2-slice quantization: src rows of `len` fp32 -> dst rows of 3*len
// int8 (orderB: [q1|q2|q1], else [q1|q1|q2]); sArr[row] = sigma = rowmax/127.
__global__ void __launch_bounds__(256)
rowquant(const float* __restrict__ src, int len, int8_t* __restrict__ dst,
         float* __restrict__ sArr, int orderB)
{
    const size_t row = blockIdx.x;
    src += row * len;
    dst += row * (size_t)(3 * len);
    const int t = threadIdx.x;

    float m = 0.f;
    for (int i = t; i < len; i += 256) m = fmaxf(m, fabsf(src[i]));
    #pragma unroll
    for (int o = 16; o > 0; o >>= 1) m = fmaxf(m, __shfl_xor_sync(~0u, m, o));
    __shared__ float sm[8];
    if ((t & 31) == 0) sm[t >> 5] = m;
    __syncthreads();
    float mm = sm[0];
    #pragma unroll
    for (int i = 1; i < 8; i++) mm = fmaxf(mm, sm[i]);

    const float s1 = mm * (1.f / 127.f);
    const float i1 = (mm > 0.f) ? (127.f / mm) : 0.f;
    const float i2 = i1 * 252.f;

    for (int i = t; i < len; i += 256) {
        float x = src[i];
        float q1 = clamp127(rintf(x * i1));
        float r = x - q1 * s1;
        float q2 = clamp127(rintf(r * i2));
        int8_t b1 = (int8_t)(int)q1, b2 = (int8_t)(int)q2;
        dst[i] = b1;
        if (orderB) { dst[len + i] = b2; dst[2 * len + i] = b1; }
        else        { dst[len + i] = b1; dst[2 * len + i] = b2; }
    }
    if (t == 0) sArr[row] = s1;
}

// Column max of |X| over ci: sX[b][n] = max_ci |X[b][ci][n]| / 127
__global__ void __launch_bounds__(256)
colmax(const float* __restrict__ X, float* __restrict__ sX)
{
    const int n = blockIdx.x * 256 + threadIdx.x;
    const int b = blockIdx.y;
    const float* p = X + (size_t)b * CIN * NPIX + n;
    float m = 0.f;
    for (int ci = 0; ci < CIN; ci++) m = fmaxf(m, fabsf(p[(size_t)ci * NPIX]));
    sX[b * NPIX + n] = m * (1.f / 127.f);
}

// Transpose + quantize: X[b][CIN][NPIX] -> XA [b][NPIX][3*CIN] A-order,
// XB (optional) B-order, using precomputed sX.
__global__ void __launch_bounds__(256)
transpose_quant(const float* __restrict__ X, const float* __restrict__ sX,
                int8_t* __restrict__ XA, int8_t* __restrict__ XB)
{
    __shared__ float t[32][33];
    const int b = blockIdx.z, n0 = blockIdx.x * 32, c0 = blockIdx.y * 32;
    const int tx = threadIdx.x & 31, ty = threadIdx.x >> 5;
    const float* Xb = X + (size_t)b * CIN * NPIX;
    #pragma unroll
    for (int r = 0; r < 4; r++)
        t[ty + r * 8][tx] = Xb[(size_t)(c0 + ty + r * 8) * NPIX + n0 + tx];
    __syncthreads();
    const size_t ob = (size_t)b * NPIX * 3 * CIN;
    #pragma unroll
    for (int r = 0; r < 4; r++) {
        const int n = n0 + ty + r * 8;
        const int c = c0 + tx;
        const float v = t[tx][ty + r * 8];
        const float s1 = sX[b * NPIX + n];
        const float i1 = (s1 > 0.f) ? (1.f / s1) : 0.f;
        float q1 = clamp127(rintf(v * i1));
        float rr = v - q1 * s1;
        float q2 = clamp127(rintf(rr * i1 * 252.f));
        int8_t b1 = (int8_t)(int)q1, b2 = (int8_t)(int)q2;
        const size_t row = ob + (size_t)n * (3 * CIN);
        XA[row + c] = b1; XA[row + CIN + c] = b1; XA[row + 2 * CIN + c] = b2;
        if (XB) { XB[row + c] = b1; XB[row + CIN + c] = b2; XB[row + 2 * CIN + c] = b1; }
    }
}

// -------- softmax: fp32 S rows -> int8 attn B-order + scale ---------------
__global__ void __launch_bounds__(256)
softmax3_q(const float* __restrict__ S, int8_t* __restrict__ A3,
           float* __restrict__ sAt)
{
    const size_t rb = (size_t)blockIdx.x * NPIX;
    const float* row = S + rb;
    int8_t* orow = A3 + (size_t)blockIdx.x * (3 * NPIX);
    const int t = threadIdx.x;
    float v[16];
    float m = -1e30f;
    #pragma unroll
    for (int i = 0; i < 16; i++) { v[i] = row[t + i * 256]; m = fmaxf(m, v[i]); }
    #pragma unroll
    for (int o = 16; o > 0; o >>= 1) m = fmaxf(m, __shfl_xor_sync(~0u, m, o));
    __shared__ float smax[8], ssum[8];
    if ((t & 31) == 0) smax[t >> 5] = m;
    __syncthreads();
    float mm = smax[0];
    #pragma unroll
    for (int i = 1; i < 8; i++) mm = fmaxf(mm, smax[i]);
    float s = 0.f;
    #pragma unroll
    for (int i = 0; i < 16; i++) { v[i] = __expf(v[i] - mm); s += v[i]; }
    #pragma unroll
    for (int o = 16; o > 0; o >>= 1) s += __shfl_xor_sync(~0u, s, o);
    if ((t & 31) == 0) ssum[t >> 5] = s;
    __syncthreads();
    float tot = 0.f;
    #pragma unroll
    for (int i = 0; i < 8; i++) tot += ssum[i];
    const float inv = 1.0f / tot;      // == max attn value (v max is 1)

    #pragma unroll
    for (int i = 0; i < 16; i++) {
        const int k = t + i * 256;
        float f = v[i] * 127.f;
        float q1 = clamp127(rintf(f));
        float q2 = clamp127(rintf((f - q1) * 252.f));
        int8_t b1 = (int8_t)(int)q1, b2 = (int8_t)(int)q2;
        orow[k] = b1;                // seg0: q1
        orow[NPIX + k] = b2;         // seg1: q2
        orow[2 * NPIX + k] = b1;     // seg2: q1
    }
    if (t == 0) sAt[blockIdx.x] = inv * (1.f / 127.f);
}

// ------------------------------- host -------------------------------------
extern "C" void kernel_launch(void* const* d_in, const int* in_sizes, int n_in,
                              void* d_out, int out_size)
{
    const float* qfeat = (const float*)d_in[0];
    const float* kfeat = (const float*)d_in[1];
    const float* Wq = (const float*)d_in[2];
    const float* bq = (const float*)d_in[3];
    const float* Wk = (const float*)d_in[4];
    const float* bk = (const float*)d_in[5];
    const float* Wv = (const float*)d_in[6];
    const float* bv = (const float*)d_in[7];
    float* out = (float*)d_out;

    void *XqA, *XkA, *XkB, *Wq3, *Wk3, *Wv3, *Qf, *Kf, *Vf, *Q3, *K3, *V3, *Sd, *A3;
    void *sXq, *sXk, *sWq, *sWk, *sWv, *sQ, *sK, *sV, *sAt;
    cudaGetSymbolAddress(&XqA, g_XqA);
    cudaGetSymbolAddress(&XkA, g_XkA);
    cudaGetSymbolAddress(&XkB, g_XkB);
    cudaGetSymbolAddress(&Wq3, g_Wq3);
    cudaGetSymbolAddress(&Wk3, g_Wk3);
    cudaGetSymbolAddress(&Wv3, g_Wv3);
    cudaGetSymbolAddress(&Qf, g_Qf);
    cudaGetSymbolAddress(&Kf, g_Kf);
    cudaGetSymbolAddress(&Vf, g_Vf);
    cudaGetSymbolAddress(&Q3, g_Q3);
    cudaGetSymbolAddress(&K3, g_K3);
    cudaGetSymbolAddress(&V3, g_V3);
    cudaGetSymbolAddress(&Sd, g_S);
    cudaGetSymbolAddress(&A3, g_A3);
    cudaGetSymbolAddress(&sXq, g_sXq);
    cudaGetSymbolAddress(&sXk, g_sXk);
    cudaGetSymbolAddress(&sWq, g_sWq);
    cudaGetSymbolAddress(&sWk, g_sWk);
    cudaGetSymbolAddress(&sWv, g_sWv);
    cudaGetSymbolAddress(&sQ, g_sQ);
    cudaGetSymbolAddress(&sK, g_sK);
    cudaGetSymbolAddress(&sV, g_sV);
    cudaGetSymbolAddress(&sAt, g_sAt);

    cudaFuncSetAttribute(gemm_s8, cudaFuncAttributeMaxDynamicSharedMemorySize, GSMEM);

    // 0) prep: quantize weights (rowquant) and inputs (colmax + transpose)
    rowquant<<<CQK, 256>>>(Wq, CIN, (int8_t*)Wq3, (float*)sWq, 1);   // B-order
    rowquant<<<CQK, 256>>>(Wk, CIN, (int8_t*)Wk3, (float*)sWk, 1);   // B-order
    rowquant<<<COUT, 256>>>(Wv, CIN, (int8_t*)Wv3, (float*)sWv, 0);  // A-order
    colmax<<<dim3(NPIX / 256, NB), 256>>>(qfeat, (float*)sXq);
    colmax<<<dim3(NPIX / 256, NB), 256>>>(kfeat, (float*)sXk);
    transpose_quant<<<dim3(NPIX / 32, CIN / 32, NB), 256>>>(
        qfeat, (const float*)sXq, (int8_t*)XqA, nullptr);
    transpose_quant<<<dim3(NPIX / 32, CIN / 32, NB), 256>>>(
        kfeat, (const float*)sXk, (int8_t*)XkA, (int8_t*)XkB);

    // 1) Q proj: Qf[b][n][c] = XqA . Wq3^T + bq  (M=4096, N=256, Kp=1536, s0=8)
    gemm_s8<<<dim3(CQK / 128, NPIX / 128, NB), 256, GSMEM>>>(
        (const int8_t*)XqA, (size_t)NPIX * 3 * CIN,
        (const int8_t*)Wq3, 0, 3 * CIN, CIN / 64,
        (float*)Qf, (size_t)CQK, (size_t)NPIX * CQK,
        (const float*)sXq, (size_t)NPIX, (const float*)sWq, 0,
        nullptr, bq, 1.0f);

    // 2) K proj
    gemm_s8<<<dim3(CQK / 128, NPIX / 128, NB), 256, GSMEM>>>(
        (const int8_t*)XkA, (size_t)NPIX * 3 * CIN,
        (const int8_t*)Wk3, 0, 3 * CIN, CIN / 64,
        (float*)Kf, (size_t)CQK, (size_t)NPIX * CQK,
        (const float*)sXk, (size_t)NPIX, (const float*)sWk, 0,
        nullptr, bk, 1.0f);

    // 3) V proj: Vf[b][o][m] = Wv3 . XkB^T + bv  (M=512, N=4096, Kp=1536, s0=8)
    gemm_s8<<<dim3(NPIX / 128, COUT / 128, NB), 256, GSMEM>>>(
        (const int8_t*)Wv3, 0,
        (const int8_t*)XkB, (size_t)NPIX * 3 * CIN, 3 * CIN, CIN / 64,
        (float*)Vf, (size_t)NPIX, (size_t)COUT * NPIX,
        (const float*)sWv, 0, (const float*)sXk, (size_t)NPIX,
        bv, nullptr, 1.0f);

    // 4) quantize Q (A-order), K (B-order), V (A-order)
    rowquant<<<NB * NPIX, 256>>>((const float*)Qf, CQK, (int8_t*)Q3, (float*)sQ, 0);
    rowquant<<<NB * NPIX, 256>>>((const float*)Kf, CQK, (int8_t*)K3, (float*)sK, 1);
    rowquant<<<NB * COUT, 256>>>((const float*)Vf, NPIX, (int8_t*)V3, (float*)sV, 0);

    // 5) sim: S[b][n][m] = (1/16) Q3 . K3^T  (M=N=4096, Kp=768, s0=4)
    gemm_s8<<<dim3(NPIX / 128, NPIX / 128, NB), 256, GSMEM>>>(
        (const int8_t*)Q3, (size_t)NPIX * 3 * CQK,
        (const int8_t*)K3, (size_t)NPIX * 3 * CQK, 3 * CQK, CQK / 64,
        (float*)Sd, (size_t)NPIX, (size_t)NPIX * NPIX,
        (const float*)sQ, (size_t)NPIX, (const float*)sK, (size_t)NPIX,
        nullptr, nullptr, 0.0625f);

    // 6) softmax -> int8 attn (B-order) + scales
    softmax3_q<<<NB * NPIX, 256>>>((const float*)Sd, (int8_t*)A3, (float*)sAt);

    // 7) ctx: out[b][o][n] = V3 . A3^T  (M=512, N=4096, Kp=12288, s0=64)
    gemm_s8<<<dim3(NPIX / 128, COUT / 128, NB), 256, GSMEM>>>(
        (const int8_t*)V3, (size_t)COUT * 3 * NPIX,
        (const int8_t*)A3, (size_t)NPIX * 3 * NPIX, 3 * NPIX, NPIX / 64,
        out, (size_t)NPIX, (size_t)COUT * NPIX,
        (const float*)sV, (size_t)COUT, (const float*)sAt, (size_t)NPIX,
        nullptr, nullptr, 1.0f);
}

// round 10
// speedup vs baseline: 2.5961x; 1.0123x over previous
#include <cuda_runtime.h>
#include <cstdint>
#include <cstddef>

#define NB    4
#define CIN   512
#define NPIX  4096
#define CQK   256
#define COUT  512

// GEMM tiling: block 128x128, K-chunk 64 int8 bytes, 3-stage cp.async pipeline
#define ROWB    80            // padded smem row bytes (64B data + 16B pad)
#define STAGE_SZ (128*ROWB*2)
#define NSTAGE  3
#define GSMEM   (STAGE_SZ*NSTAGE)
#define INV252  (1.0f/252.0f)
#define SSCALE  2048.0f
#define INVSSCALE (1.0f/2048.0f)

// -------------------- scratch (device globals) ----------------------------
// Physical layout everywhere: [q1 | q2] (2 segments). The GEMM loader remaps
// logical 3-segment orders (A: [q1|q1|q2], B: [q1|q2|q1]) onto this storage.
__device__ int8_t  g_Xq2[(size_t)NB*NPIX*2*CIN];
__device__ int8_t  g_Xk2[(size_t)NB*NPIX*2*CIN];
__device__ int8_t  g_Wq2[CQK*2*CIN];
__device__ int8_t  g_Wk2[CQK*2*CIN];
__device__ int8_t  g_Wv2[COUT*2*CIN];
__device__ float   g_Qf[(size_t)NB*NPIX*CQK];
__device__ float   g_Kf[(size_t)NB*NPIX*CQK];
__device__ float   g_Vf[(size_t)NB*COUT*NPIX];
__device__ int8_t  g_Q2[(size_t)NB*NPIX*2*CQK];
__device__ int8_t  g_K2[(size_t)NB*NPIX*2*CQK];
__device__ int8_t  g_V2[(size_t)NB*COUT*2*NPIX];
__device__ int16_t g_S [(size_t)NB*NPIX*NPIX];           // sim, int16 * SSCALE
__device__ int8_t  g_A2[(size_t)NB*NPIX*2*NPIX];
// scales (sigma = rowmax/127 ; x ~= sigma*(q1 + q2/252))
__device__ float g_sXq[NB*NPIX], g_sXk[NB*NPIX];
__device__ float g_sWq[CQK], g_sWk[CQK], g_sWv[COUT];
__device__ float g_sQ[NB*NPIX], g_sK[NB*NPIX], g_sV[NB*COUT], g_sAt[NB*NPIX];

// -------------------- PTX helpers -----------------------------------------
__device__ __forceinline__ uint32_t s2u(const void* p) {
    uint32_t a;
    asm("{ .reg .u64 t; cvta.to.shared.u64 t, %1; cvt.u32.u64 %0, t; }" : "=r"(a) : "l"(p));
    return a;
}
__device__ __forceinline__ void cp16(uint32_t s, const void* g) {
    asm volatile("cp.async.cg.shared.global [%0], [%1], 16;" :: "r"(s), "l"(g));
}
#define CP_COMMIT() asm volatile("cp.async.commit_group;" ::: "memory")
#define CP_WAIT1()  asm volatile("cp.async.wait_group 1;" ::: "memory")

__device__ __forceinline__ void ldm4(uint32_t& r0, uint32_t& r1, uint32_t& r2, uint32_t& r3,
                                     uint32_t a) {
    asm volatile("ldmatrix.sync.aligned.m8n8.x4.shared.b16 {%0,%1,%2,%3}, [%4];"
                 : "=r"(r0), "=r"(r1), "=r"(r2), "=r"(r3) : "r"(a));
}
__device__ __forceinline__ void mma16832(int* d, const uint32_t* a, uint32_t b0, uint32_t b1) {
    asm volatile(
      "mma.sync.aligned.m16n8k32.row.col.s32.s8.s8.s32 "
      "{%0,%1,%2,%3},{%4,%5,%6,%7},{%8,%9},{%0,%1,%2,%3};"
      : "+r"(d[0]), "+r"(d[1]), "+r"(d[2]), "+r"(d[3])
      : "r"(a[0]), "r"(a[1]), "r"(a[2]), "r"(a[3]), "r"(b0), "r"(b1));
}

// -------------------- canonical int8 Ozaki GEMM ---------------------------
// D[M,N] = scale * sigA[m]*sigB[n]*(acc0 + acc1/252) + bias_row[m] + bias_col[n]
// A, B physical rows: [q1 | q2], rowlen = 2K bytes. Logical inner loop runs
// 3K: A segs [q1|q1|q2], B segs [q1|q2|q1] via index remap. Logical chunks
// < K/64 accumulate in acc0 (q1*q1), the rest in acc1 (cross terms / 252).
// EPI 0: fp32 out.  EPI 1: int16 out (value * SSCALE, clamped).
template<int EPI>
__global__ void __launch_bounds__(256)
gemm_s8(const int8_t* __restrict__ A, size_t sA,
        const int8_t* __restrict__ B, size_t sB,
        int K,
        float* __restrict__ Cf, int16_t* __restrict__ Cs, size_t ldc, size_t sC,
        const float* __restrict__ sAarr, size_t sAstr,
        const float* __restrict__ sBarr, size_t sBstr,
        const float* __restrict__ bias_row, const float* __restrict__ bias_col,
        float scale)
{
    extern __shared__ __align__(128) char smem[];
    const uint32_t sb = s2u(smem);
    const int tid = threadIdx.x, lane = tid & 31, wid = tid >> 5;
    const int wm0 = (wid >> 2) * 64;
    const int wn0 = (wid & 3) * 32;
    const int m0 = blockIdx.y * 128, n0 = blockIdx.x * 128, z = blockIdx.z;

    const int n1 = K / 64;          // chunks per segment
    const int nk = 3 * n1;          // logical chunk count
    const int rowlen = 2 * K;       // physical row bytes

    A += (size_t)z * sA + (size_t)m0 * rowlen;
    B += (size_t)z * sB + (size_t)n0 * rowlen;

    const int r0 = tid >> 2;
    const int c0 = tid & 3;

    auto load_stage = [&](int st, int kc) {
        const int ca = (kc < n1) ? kc : kc - n1;          // A: [q1|q1|q2]
        const int cb = (kc < 2 * n1) ? kc : kc - 2 * n1;  // B: [q1|q2|q1]
        const int8_t* ga = A + (size_t)ca * 64;
        const int8_t* gb = B + (size_t)cb * 64;
        uint32_t sa = sb + st * STAGE_SZ;
        uint32_t sbm = sa + 128 * ROWB;
        cp16(sa  + r0 * ROWB + c0 * 16,        ga + (size_t)r0 * rowlen + c0 * 16);
        cp16(sa  + (r0 + 64) * ROWB + c0 * 16, ga + (size_t)(r0 + 64) * rowlen + c0 * 16);
        cp16(sbm + r0 * ROWB + c0 * 16,        gb + (size_t)r0 * rowlen + c0 * 16);
        cp16(sbm + (r0 + 64) * ROWB + c0 * 16, gb + (size_t)(r0 + 64) * rowlen + c0 * 16);
    };

    int acc0[4][4][4], acc1[4][4][4];
    #pragma unroll
    for (int i = 0; i < 4; i++)
        #pragma unroll
        for (int j = 0; j < 4; j++)
            #pragma unroll
            for (int q = 0; q < 4; q++) { acc0[i][j][q] = 0; acc1[i][j][q] = 0; }

    load_stage(0, 0); CP_COMMIT();
    load_stage(1, 1); CP_COMMIT();

    const int arow = wm0 + (lane & 15);
    const int acsel = (lane >> 4);
    const int brow = wn0 + (lane & 7) + ((lane >> 4) & 1) * 8;
    const int bcsel = (lane >> 3) & 1;

    for (int k = 0; k < nk; k++) {
        CP_WAIT1();
        __syncthreads();
        if (k + 2 < nk) load_stage((k + 2) % NSTAGE, k + 2);
        CP_COMMIT();

        const uint32_t sa = sb + (k % NSTAGE) * STAGE_SZ;
        const uint32_t sbm = sa + 128 * ROWB;

        #pragma unroll
        for (int ks = 0; ks < 2; ks++) {
            uint32_t a[4][4], bfr[2][4];
            const uint32_t ac = (ks * 2 + acsel) * 16;
            #pragma unroll
            for (int i = 0; i < 4; i++)
                ldm4(a[i][0], a[i][1], a[i][2], a[i][3],
                     sa + (arow + i * 16) * ROWB + ac);
            const uint32_t bc = (ks * 2 + bcsel) * 16;
            #pragma unroll
            for (int j = 0; j < 2; j++)
                ldm4(bfr[j][0], bfr[j][1], bfr[j][2], bfr[j][3],
                     sbm + (brow + j * 16) * ROWB + bc);
            if (k < n1) {
                #pragma unroll
                for (int i = 0; i < 4; i++)
                    #pragma unroll
                    for (int jn = 0; jn < 4; jn++)
                        mma16832(acc0[i][jn], a[i],
                                 bfr[jn >> 1][(jn & 1) * 2], bfr[jn >> 1][(jn & 1) * 2 + 1]);
            } else {
                #pragma unroll
                for (int i = 0; i < 4; i++)
                    #pragma unroll
                    for (int jn = 0; jn < 4; jn++)
                        mma16832(acc1[i][jn], a[i],
                                 bfr[jn >> 1][(jn & 1) * 2], bfr[jn >> 1][(jn & 1) * 2 + 1]);
            }
        }
        __syncthreads();
    }

    // -------- epilogue --------
    const int mb = m0 + wm0 + (lane >> 2);
    const int nb = n0 + wn0 + (lane & 3) * 2;
    #pragma unroll
    for (int i = 0; i < 4; i++) {
        #pragma unroll
        for (int half = 0; half < 2; half++) {
            const int m = mb + i * 16 + half * 8;
            const float sAm = sAarr[z * sAstr + m] * scale;
            const float br = bias_row ? bias_row[m] : 0.f;
            #pragma unroll
            for (int jn = 0; jn < 4; jn++) {
                const int n = nb + jn * 8;
                float f0 = (float)acc0[i][jn][half * 2 + 0]
                         + (float)acc1[i][jn][half * 2 + 0] * INV252;
                float f1 = (float)acc0[i][jn][half * 2 + 1]
                         + (float)acc1[i][jn][half * 2 + 1] * INV252;
                float v0 = f0 * sAm * sBarr[z * sBstr + n] + br;
                float v1 = f1 * sAm * sBarr[z * sBstr + n + 1] + br;
                if (bias_col) { v0 += bias_col[n]; v1 += bias_col[n + 1]; }
                if (EPI == 0) {
                    *(float2*)&Cf[(size_t)z * sC + (size_t)m * ldc + n] = make_float2(v0, v1);
                } else {
                    float q0 = fminf(fmaxf(v0 * SSCALE, -32000.f), 32000.f);
                    float q1 = fminf(fmaxf(v1 * SSCALE, -32000.f), 32000.f);
                    short2 o;
                    o.x = (short)(int)rintf(q0);
                    o.y = (short)(int)rintf(q1);
                    *(short2*)&Cs[(size_t)z * sC + (size_t)m * ldc + n] = o;
                }
            }
        }
    }
}

// -------------------- quantization helpers --------------------------------
__device__ __forceinline__ float clamp127(float q) {
    return fminf(127.f, fmaxf(-127.f, q));
}

// Row-wise 2-slice quantization: src rows of `len` fp32 -> dst rows of 2*len
// int8 [q1 | q2]; sArr[row] = sigma = rowmax/127.
__global__ void __launch_bounds__(256)
rowquant(const float* __restrict__ src, int len, int8_t* __restrict__ dst,
         float* __restrict__ sArr)
{
    const size_t row = blockIdx.x;
    src += row * len;
    dst += row * (size_t)(2 * len);
    const int t = threadIdx.x;

    float m = 0.f;
    for (int i = t; i < len; i += 256) m = fmaxf(m, fabsf(src[i]));
    #pragma unroll
    for (int o = 16; o > 0; o >>= 1) m = fmaxf(m, __shfl_xor_sync(~0u, m, o));
    __shared__ float sm[8];
    if ((t & 31) == 0) sm[t >> 5] = m;
    __syncthreads();
    float mm = sm[0];
    #pragma unroll
    for (int i = 1; i < 8; i++) mm = fmaxf(mm, sm[i]);

    const float s1 = mm * (1.f / 127.f);
    const float i1 = (mm > 0.f) ? (127.f / mm) : 0.f;
    const float i2 = i1 * 252.f;

    for (int i = t; i < len; i += 256) {
        float x = src[i];
        float q1 = clamp127(rintf(x * i1));
        float r = x - q1 * s1;
        float q2 = clamp127(rintf(r * i2));
        dst[i] = (int8_t)(int)q1;
        dst[len + i] = (int8_t)(int)q2;
    }
    if (t == 0) sArr[row] = s1;
}

// Column max of |X| over ci: sX[b][n] = max_ci |X[b][ci][n]| / 127
__global__ void __launch_bounds__(256)
colmax(const float* __restrict__ X, float* __restrict__ sX)
{
    const int n = blockIdx.x * 256 + threadIdx.x;
    const int b = blockIdx.y;
    const float* p = X + (size_t)b * CIN * NPIX + n;
    float m = 0.f;
    for (int ci = 0; ci < CIN; ci++) m = fmaxf(m, fabsf(p[(size_t)ci * NPIX]));
    sX[b * NPIX + n] = m * (1.f / 127.f);
}

// Transpose + quantize: X[b][CIN][NPIX] -> X2 [b][NPIX][2*CIN] ([q1|q2])
__global__ void __launch_bounds__(256)
transpose_quant(const float* __restrict__ X, const float* __restrict__ sX,
                int8_t* __restrict__ X2)
{
    __shared__ float t[32][33];
    const int b = blockIdx.z, n0 = blockIdx.x * 32, c0 = blockIdx.y * 32;
    const int tx = threadIdx.x & 31, ty = threadIdx.x >> 5;
    const float* Xb = X + (size_t)b * CIN * NPIX;
    #pragma unroll
    for (int r = 0; r < 4; r++)
        t[ty + r * 8][tx] = Xb[(size_t)(c0 + ty + r * 8) * NPIX + n0 + tx];
    __syncthreads();
    const size_t ob = (size_t)b * NPIX * 2 * CIN;
    #pragma unroll
    for (int r = 0; r < 4; r++) {
        const int n = n0 + ty + r * 8;
        const int c = c0 + tx;
        const float v = t[tx][ty + r * 8];
        const float s1 = sX[b * NPIX + n];
        const float i1 = (s1 > 0.f) ? (1.f / s1) : 0.f;
        float q1 = clamp127(rintf(v * i1));
        float rr = v - q1 * s1;
        float q2 = clamp127(rintf(rr * i1 * 252.f));
        const size_t row = ob + (size_t)n * (2 * CIN);
        X2[row + c] = (int8_t)(int)q1;
        X2[row + CIN + c] = (int8_t)(int)q2;
    }
}

// -------- softmax: int16 S rows -> int8 attn [q1|q2] + scale ---------------
__global__ void __launch_bounds__(256)
softmax2_q(const int16_t* __restrict__ S, int8_t* __restrict__ A2,
           float* __restrict__ sAt)
{
    const size_t rb = (size_t)blockIdx.x * NPIX;
    const int16_t* row = S + rb;
    int8_t* orow = A2 + (size_t)blockIdx.x * (2 * NPIX);
    const int t = threadIdx.x;
    float v[16];
    float m = -1e30f;
    #pragma unroll
    for (int i = 0; i < 16; i++) {
        v[i] = (float)row[t + i * 256] * INVSSCALE;
        m = fmaxf(m, v[i]);
    }
    #pragma unroll
    for (int o = 16; o > 0; o >>= 1) m = fmaxf(m, __shfl_xor_sync(~0u, m, o));
    __shared__ float smax[8], ssum[8];
    if ((t & 31) == 0) smax[t >> 5] = m;
    __syncthreads();
    float mm = smax[0];
    #pragma unroll
    for (int i = 1; i < 8; i++) mm = fmaxf(mm, smax[i]);
    float s = 0.f;
    #pragma unroll
    for (int i = 0; i < 16; i++) { v[i] = __expf(v[i] - mm); s += v[i]; }
    #pragma unroll
    for (int o = 16; o > 0; o >>= 1) s += __shfl_xor_sync(~0u, s, o);
    if ((t & 31) == 0) ssum[t >> 5] = s;
    __syncthreads();
    float tot = 0.f;
    #pragma unroll
    for (int i = 0; i < 8; i++) tot += ssum[i];
    const float inv = 1.0f / tot;      // max attn value (max v is 1)

    #pragma unroll
    for (int i = 0; i < 16; i++) {
        const int k = t + i * 256;
        float f = v[i] * 127.f;
        float q1 = clamp127(rintf(f));
        float q2 = clamp127(rintf((f - q1) * 252.f));
        orow[k] = (int8_t)(int)q1;
        orow[NPIX + k] = (int8_t)(int)q2;
    }
    if (t == 0) sAt[blockIdx.x] = inv * (1.f / 127.f);
}

// ------------------------------- host -------------------------------------
extern "C" void kernel_launch(void* const* d_in, const int* in_sizes, int n_in,
                              void* d_out, int out_size)
{
    const float* qfeat = (const float*)d_in[0];
    const float* kfeat = (const float*)d_in[1];
    const float* Wq = (const float*)d_in[2];
    const float* bq = (const float*)d_in[3];
    const float* Wk = (const float*)d_in[4];
    const float* bk = (const float*)d_in[5];
    const float* Wv = (const float*)d_in[6];
    const float* bv = (const float*)d_in[7];
    float* out = (float*)d_out;

    void *Xq2, *Xk2, *Wq2, *Wk2, *Wv2, *Qf, *Kf, *Vf, *Q2, *K2, *V2, *Sd, *A2;
    void *sXq, *sXk, *sWq, *sWk, *sWv, *sQ, *sK, *sV, *sAt;
    cudaGetSymbolAddress(&Xq2, g_Xq2);
    cudaGetSymbolAddress(&Xk2, g_Xk2);
    cudaGetSymbolAddress(&Wq2, g_Wq2);
    cudaGetSymbolAddress(&Wk2, g_Wk2);
    cudaGetSymbolAddress(&Wv2, g_Wv2);
    cudaGetSymbolAddress(&Qf, g_Qf);
    cudaGetSymbolAddress(&Kf, g_Kf);
    cudaGetSymbolAddress(&Vf, g_Vf);
    cudaGetSymbolAddress(&Q2, g_Q2);
    cudaGetSymbolAddress(&K2, g_K2);
    cudaGetSymbolAddress(&V2, g_V2);
    cudaGetSymbolAddress(&Sd, g_S);
    cudaGetSymbolAddress(&A2, g_A2);
    cudaGetSymbolAddress(&sXq, g_sXq);
    cudaGetSymbolAddress(&sXk, g_sXk);
    cudaGetSymbolAddress(&sWq, g_sWq);
    cudaGetSymbolAddress(&sWk, g_sWk);
    cudaGetSymbolAddress(&sWv, g_sWv);
    cudaGetSymbolAddress(&sQ, g_sQ);
    cudaGetSymbolAddress(&sK, g_sK);
    cudaGetSymbolAddress(&sV, g_sV);
    cudaGetSymbolAddress(&sAt, g_sAt);

    cudaFuncSetAttribute(gemm_s8<0>, cudaFuncAttributeMaxDynamicSharedMemorySize, GSMEM);
    cudaFuncSetAttribute(gemm_s8<1>, cudaFuncAttributeMaxDynamicSharedMemorySize, GSMEM);

    // 0) prep: quantize weights, inputs (colmax + transpose)
    rowquant<<<CQK, 256>>>(Wq, CIN, (int8_t*)Wq2, (float*)sWq);
    rowquant<<<CQK, 256>>>(Wk, CIN, (int8_t*)Wk2, (float*)sWk);
    rowquant<<<COUT, 256>>>(Wv, CIN, (int8_t*)Wv2, (float*)sWv);
    colmax<<<dim3(NPIX / 256, NB), 256>>>(qfeat, (float*)sXq);
    colmax<<<dim3(NPIX / 256, NB), 256>>>(kfeat, (float*)sXk);
    transpose_quant<<<dim3(NPIX / 32, CIN / 32, NB), 256>>>(
        qfeat, (const float*)sXq, (int8_t*)Xq2);
    transpose_quant<<<dim3(NPIX / 32, CIN / 32, NB), 256>>>(
        kfeat, (const float*)sXk, (int8_t*)Xk2);

    // 1) Q proj: Qf[b][n][c] = Xq2 . Wq2^T + bq  (M=4096, N=256, K=512)
    gemm_s8<0><<<dim3(CQK / 128, NPIX / 128, NB), 256, GSMEM>>>(
        (const int8_t*)Xq2, (size_t)NPIX * 2 * CIN,
        (const int8_t*)Wq2, 0, CIN,
        (float*)Qf, nullptr, (size_t)CQK, (size_t)NPIX * CQK,
        (const float*)sXq, (size_t)NPIX, (const float*)sWq, 0,
        nullptr, bq, 1.0f);

    // 2) K proj
    gemm_s8<0><<<dim3(CQK / 128, NPIX / 128, NB), 256, GSMEM>>>(
        (const int8_t*)Xk2, (size_t)NPIX * 2 * CIN,
        (const int8_t*)Wk2, 0, CIN,
        (float*)Kf, nullptr, (size_t)CQK, (size_t)NPIX * CQK,
        (const float*)sXk, (size_t)NPIX, (const float*)sWk, 0,
        nullptr, bk, 1.0f);

    // 3) V proj: Vf[b][o][m] = Wv2 . Xk2^T + bv  (M=512, N=4096, K=512)
    gemm_s8<0><<<dim3(NPIX / 128, COUT / 128, NB), 256, GSMEM>>>(
        (const int8_t*)Wv2, 0,
        (const int8_t*)Xk2, (size_t)NPIX * 2 * CIN, CIN,
        (float*)Vf, nullptr, (size_t)NPIX, (size_t)COUT * NPIX,
        (const float*)sWv, 0, (const float*)sXk, (size_t)NPIX,
        bv, nullptr, 1.0f);

    // 4) quantize Q, K, V (shared [q1|q2] layout)
    rowquant<<<NB * NPIX, 256>>>((const float*)Qf, CQK, (int8_t*)Q2, (float*)sQ);
    rowquant<<<NB * NPIX, 256>>>((const float*)Kf, CQK, (int8_t*)K2, (float*)sK);
    rowquant<<<NB * COUT, 256>>>((const float*)Vf, NPIX, (int8_t*)V2, (float*)sV);

    // 5) sim: S[b][n][m] = int16( (1/16) Q2 . K2^T * SSCALE )  (M=N=4096, K=256)
    gemm_s8<1><<<dim3(NPIX / 128, NPIX / 128, NB), 256, GSMEM>>>(
        (const int8_t*)Q2, (size_t)NPIX * 2 * CQK,
        (const int8_t*)K2, (size_t)NPIX * 2 * CQK, CQK,
        nullptr, (int16_t*)Sd, (size_t)NPIX, (size_t)NPIX * NPIX,
        (const float*)sQ, (size_t)NPIX, (const float*)sK, (size_t)NPIX,
        nullptr, nullptr, 0.0625f);

    // 6) softmax -> int8 attn [q1|q2] + scales
    softmax2_q<<<NB * NPIX, 256>>>((const int16_t*)Sd, (int8_t*)A2, (float*)sAt);

    // 7) ctx: out[b][o][n] = V2 . A2^T  (M=512, N=4096, K=4096)
    gemm_s8<0><<<dim3(NPIX / 128, COUT / 128, NB), 256, GSMEM>>>(
        (const int8_t*)V2, (size_t)COUT * 2 * NPIX,
        (const int8_t*)A2, (size_t)NPIX * 2 * NPIX, NPIX,
        out, nullptr, (size_t)NPIX, (size_t)COUT * NPIX,
        (const float*)sV, (size_t)COUT, (const float*)sAt, (size_t)NPIX,
        nullptr, nullptr, 1.0f);
}

// round 12
// speedup vs baseline: 3.0034x; 1.1569x over previous
#include <cuda_runtime.h>
#include <cstdint>
#include <cstddef>

#define NB    4
#define CIN   512
#define NPIX  4096
#define CQK   256
#define COUT  512

// GEMM tiling: block 128x128, K-chunk 128 int8 bytes, 3-stage cp.async pipeline
#define ROWB    144           // padded smem row bytes (128B data + 16B pad)
#define STAGE_SZ (128*ROWB*2) // 36864 B
#define NSTAGE  3
#define GSMEM   (STAGE_SZ*NSTAGE)   // 110592 B
#define INV252  (1.0f/252.0f)
#define SSCALE  2048.0f
#define INVSSCALE (1.0f/2048.0f)

// -------------------- scratch (device globals) ----------------------------
// Physical layout everywhere: [q1 | q2]. GEMM loader remaps logical 3-segment
// orders (A: [q1|q1|q2], B: [q1|q2|q1]) onto this storage.
__device__ int8_t  g_Xq2[(size_t)NB*NPIX*2*CIN];
__device__ int8_t  g_Xk2[(size_t)NB*NPIX*2*CIN];
__device__ int8_t  g_Wq2[CQK*2*CIN];
__device__ int8_t  g_Wk2[CQK*2*CIN];
__device__ int8_t  g_Wv2[COUT*2*CIN];
__device__ float   g_Qf[(size_t)NB*NPIX*CQK];
__device__ float   g_Kf[(size_t)NB*NPIX*CQK];
__device__ float   g_Vf[(size_t)NB*COUT*NPIX];
__device__ int8_t  g_Q2[(size_t)NB*NPIX*2*CQK];
__device__ int8_t  g_K2[(size_t)NB*NPIX*2*CQK];
__device__ int8_t  g_V2[(size_t)NB*COUT*2*NPIX];
__device__ int16_t g_S [(size_t)NB*NPIX*NPIX];
__device__ int8_t  g_A2[(size_t)NB*NPIX*2*NPIX];
__device__ float g_sXq[NB*NPIX], g_sXk[NB*NPIX];
__device__ float g_sWq[CQK], g_sWk[CQK], g_sWv[COUT];
__device__ float g_sQ[NB*NPIX], g_sK[NB*NPIX], g_sV[NB*COUT], g_sAt[NB*NPIX];

// -------------------- PTX helpers -----------------------------------------
__device__ __forceinline__ uint32_t s2u(const void* p) {
    uint32_t a;
    asm("{ .reg .u64 t; cvta.to.shared.u64 t, %1; cvt.u32.u64 %0, t; }" : "=r"(a) : "l"(p));
    return a;
}
__device__ __forceinline__ void cp16(uint32_t s, const void* g) {
    asm volatile("cp.async.cg.shared.global [%0], [%1], 16;" :: "r"(s), "l"(g));
}
#define CP_COMMIT() asm volatile("cp.async.commit_group;" ::: "memory")
#define CP_WAIT1()  asm volatile("cp.async.wait_group 1;" ::: "memory")

__device__ __forceinline__ void ldm4(uint32_t& r0, uint32_t& r1, uint32_t& r2, uint32_t& r3,
                                     uint32_t a) {
    asm volatile("ldmatrix.sync.aligned.m8n8.x4.shared.b16 {%0,%1,%2,%3}, [%4];"
                 : "=r"(r0), "=r"(r1), "=r"(r2), "=r"(r3) : "r"(a));
}
__device__ __forceinline__ void mma16832(int* d, const uint32_t* a, uint32_t b0, uint32_t b1) {
    asm volatile(
      "mma.sync.aligned.m16n8k32.row.col.s32.s8.s8.s32 "
      "{%0,%1,%2,%3},{%4,%5,%6,%7},{%8,%9},{%0,%1,%2,%3};"
      : "+r"(d[0]), "+r"(d[1]), "+r"(d[2]), "+r"(d[3])
      : "r"(a[0]), "r"(a[1]), "r"(a[2]), "r"(a[3]), "r"(b0), "r"(b1));
}

// -------------------- canonical int8 Ozaki GEMM ---------------------------
// D[M,N] = scale * sigA[m]*sigB[n]*(acc0 + acc1/252) + bias_row[m] + bias_col[n]
// Physical rows [q1|q2] (2K bytes). Logical chunks of 128B: A [q1|q1|q2],
// B [q1|q2|q1] via remap; chunks < K/128 -> acc0, rest -> acc1.
// EPI 0: fp32 out.  EPI 1: int16 out (value * SSCALE, clamped).
template<int EPI>
__global__ void __launch_bounds__(256)
gemm_s8(const int8_t* __restrict__ A, size_t sA,
        const int8_t* __restrict__ B, size_t sB,
        int K,
        float* __restrict__ Cf, int16_t* __restrict__ Cs, size_t ldc, size_t sC,
        const float* __restrict__ sAarr, size_t sAstr,
        const float* __restrict__ sBarr, size_t sBstr,
        const float* __restrict__ bias_row, const float* __restrict__ bias_col,
        float scale)
{
    extern __shared__ __align__(128) char smem[];
    const uint32_t sb = s2u(smem);
    const int tid = threadIdx.x, lane = tid & 31, wid = tid >> 5;
    const int wm0 = (wid >> 2) * 64;
    const int wn0 = (wid & 3) * 32;
    const int m0 = blockIdx.y * 128, n0 = blockIdx.x * 128, z = blockIdx.z;

    const int n1 = K / 128;         // 128B chunks per segment
    const int nk = 3 * n1;          // logical chunk count
    const int rowlen = 2 * K;       // physical row bytes

    A += (size_t)z * sA + (size_t)m0 * rowlen;
    B += (size_t)z * sB + (size_t)n0 * rowlen;

    auto load_stage = [&](int st, int kc) {
        const int ca = (kc < n1) ? kc : kc - n1;          // A: [q1|q1|q2]
        const int cb = (kc < 2 * n1) ? kc : kc - 2 * n1;  // B: [q1|q2|q1]
        const int8_t* ga = A + (size_t)ca * 128;
        const int8_t* gb = B + (size_t)cb * 128;
        uint32_t sa = sb + st * STAGE_SZ;
        uint32_t sbm = sa + 128 * ROWB;
        #pragma unroll
        for (int i = 0; i < 4; i++) {
            const int idx = tid + i * 256;       // 0..1023 over 128 rows x 8 chunks
            const int row = idx >> 3, ch = idx & 7;
            cp16(sa  + row * ROWB + ch * 16, ga + (size_t)row * rowlen + ch * 16);
            cp16(sbm + row * ROWB + ch * 16, gb + (size_t)row * rowlen + ch * 16);
        }
    };

    int acc0[4][4][4], acc1[4][4][4];
    #pragma unroll
    for (int i = 0; i < 4; i++)
        #pragma unroll
        for (int j = 0; j < 4; j++)
            #pragma unroll
            for (int q = 0; q < 4; q++) { acc0[i][j][q] = 0; acc1[i][j][q] = 0; }

    load_stage(0, 0); CP_COMMIT();
    load_stage(1, 1); CP_COMMIT();

    const int arow = wm0 + (lane & 15);
    const int acsel = (lane >> 4);
    const int brow = wn0 + (lane & 7) + ((lane >> 4) & 1) * 8;
    const int bcsel = (lane >> 3) & 1;

    for (int k = 0; k < nk; k++) {
        CP_WAIT1();
        __syncthreads();
        if (k + 2 < nk) load_stage((k + 2) % NSTAGE, k + 2);
        CP_COMMIT();

        const uint32_t sa = sb + (k % NSTAGE) * STAGE_SZ;
        const uint32_t sbm = sa + 128 * ROWB;

        #pragma unroll
        for (int ks = 0; ks < 4; ks++) {          // 4 x 32B k-steps per 128B chunk
            uint32_t a[4][4], bfr[2][4];
            const uint32_t ac = (ks * 2 + acsel) * 16;
            #pragma unroll
            for (int i = 0; i < 4; i++)
                ldm4(a[i][0], a[i][1], a[i][2], a[i][3],
                     sa + (arow + i * 16) * ROWB + ac);
            const uint32_t bc = (ks * 2 + bcsel) * 16;
            #pragma unroll
            for (int j = 0; j < 2; j++)
                ldm4(bfr[j][0], bfr[j][1], bfr[j][2], bfr[j][3],
                     sbm + (brow + j * 16) * ROWB + bc);
            if (k < n1) {
                #pragma unroll
                for (int i = 0; i < 4; i++)
                    #pragma unroll
                    for (int jn = 0; jn < 4; jn++)
                        mma16832(acc0[i][jn], a[i],
                                 bfr[jn >> 1][(jn & 1) * 2], bfr[jn >> 1][(jn & 1) * 2 + 1]);
            } else {
                #pragma unroll
                for (int i = 0; i < 4; i++)
                    #pragma unroll
                    for (int jn = 0; jn < 4; jn++)
                        mma16832(acc1[i][jn], a[i],
                                 bfr[jn >> 1][(jn & 1) * 2], bfr[jn >> 1][(jn & 1) * 2 + 1]);
            }
        }
        __syncthreads();
    }

    // -------- epilogue --------
    const int mb = m0 + wm0 + (lane >> 2);
    const int nb = n0 + wn0 + (lane & 3) * 2;
    #pragma unroll
    for (int i = 0; i < 4; i++) {
        #pragma unroll
        for (int half = 0; half < 2; half++) {
            const int m = mb + i * 16 + half * 8;
            const float sAm = sAarr[z * sAstr + m] * scale;
            const float br = bias_row ? bias_row[m] : 0.f;
            #pragma unroll
            for (int jn = 0; jn < 4; jn++) {
                const int n = nb + jn * 8;
                float f0 = (float)acc0[i][jn][half * 2 + 0]
                         + (float)acc1[i][jn][half * 2 + 0] * INV252;
                float f1 = (float)acc0[i][jn][half * 2 + 1]
                         + (float)acc1[i][jn][half * 2 + 1] * INV252;
                float v0 = f0 * sAm * sBarr[z * sBstr + n] + br;
                float v1 = f1 * sAm * sBarr[z * sBstr + n + 1] + br;
                if (bias_col) { v0 += bias_col[n]; v1 += bias_col[n + 1]; }
                if (EPI == 0) {
                    *(float2*)&Cf[(size_t)z * sC + (size_t)m * ldc + n] = make_float2(v0, v1);
                } else {
                    float q0 = fminf(fmaxf(v0 * SSCALE, -32000.f), 32000.f);
                    float q1 = fminf(fmaxf(v1 * SSCALE, -32000.f), 32000.f);
                    short2 o;
                    o.x = (short)(int)rintf(q0);
                    o.y = (short)(int)rintf(q1);
                    *(short2*)&Cs[(size_t)z * sC + (size_t)m * ldc + n] = o;
                }
            }
        }
    }
}

// -------------------- quantization helpers --------------------------------
__device__ __forceinline__ float clamp127(float q) {
    return fminf(127.f, fmaxf(-127.f, q));
}

// Shared row-quant body: src row of `len` fp32 -> dst row of 2*len int8 [q1|q2]
__device__ __forceinline__ void rowquant_body(const float* __restrict__ src, int len,
                                              int8_t* __restrict__ dst,
                                              float* __restrict__ sOut)
{
    const int t = threadIdx.x;
    float m = 0.f;
    for (int i = t; i < len; i += 256) m = fmaxf(m, fabsf(src[i]));
    #pragma unroll
    for (int o = 16; o > 0; o >>= 1) m = fmaxf(m, __shfl_xor_sync(~0u, m, o));
    __shared__ float sm[8];
    if ((t & 31) == 0) sm[t >> 5] = m;
    __syncthreads();
    float mm = sm[0];
    #pragma unroll
    for (int i = 1; i < 8; i++) mm = fmaxf(mm, sm[i]);

    const float s1 = mm * (1.f / 127.f);
    const float i1 = (mm > 0.f) ? (127.f / mm) : 0.f;
    const float i2 = i1 * 252.f;

    for (int i = t; i < len; i += 256) {
        float x = src[i];
        float q1 = clamp127(rintf(x * i1));
        float r = x - q1 * s1;
        float q2 = clamp127(rintf(r * i2));
        dst[i] = (int8_t)(int)q1;
        dst[len + i] = (int8_t)(int)q2;
    }
    if (t == 0) *sOut = s1;
}

// Merged weight quantization: Wq (256 rows) | Wk (256) | Wv (512), len=CIN
__global__ void __launch_bounds__(256)
rowquantW(const float* __restrict__ Wq, const float* __restrict__ Wk,
          const float* __restrict__ Wv,
          int8_t* __restrict__ Wq2, int8_t* __restrict__ Wk2, int8_t* __restrict__ Wv2,
          float* __restrict__ sWq, float* __restrict__ sWk, float* __restrict__ sWv)
{
    const int r = blockIdx.x;
    const float* src; int8_t* dst; float* sOut;
    if (r < CQK)            { src = Wq + (size_t)r * CIN;          dst = Wq2 + (size_t)r * 2 * CIN;          sOut = sWq + r; }
    else if (r < 2 * CQK)   { int rr = r - CQK;   src = Wk + (size_t)rr * CIN; dst = Wk2 + (size_t)rr * 2 * CIN; sOut = sWk + rr; }
    else                    { int rr = r - 2*CQK; src = Wv + (size_t)rr * CIN; dst = Wv2 + (size_t)rr * 2 * CIN; sOut = sWv + rr; }
    rowquant_body(src, CIN, dst, sOut);
}

// Merged Q/K quantization: grid.x = 2*NB*NPIX rows of len CQK
__global__ void __launch_bounds__(256)
rowquantQK(const float* __restrict__ Qf, const float* __restrict__ Kf,
           int8_t* __restrict__ Q2, int8_t* __restrict__ K2,
           float* __restrict__ sQ, float* __restrict__ sK)
{
    const size_t r = blockIdx.x;
    const size_t nrows = (size_t)NB * NPIX;
    if (r < nrows)
        rowquant_body(Qf + r * CQK, CQK, Q2 + r * 2 * CQK, sQ + r);
    else {
        const size_t rr = r - nrows;
        rowquant_body(Kf + rr * CQK, CQK, K2 + rr * 2 * CQK, sK + rr);
    }
}

__global__ void __launch_bounds__(256)
rowquantV(const float* __restrict__ Vf, int8_t* __restrict__ V2, float* __restrict__ sV)
{
    const size_t r = blockIdx.x;
    rowquant_body(Vf + r * NPIX, NPIX, V2 + r * 2 * NPIX, sV + r);
}

// Chunked column-max with atomicMax (non-negative floats as ints: monotone;
// deterministic across graph replays since inputs are identical).
// grid (NPIX/256, NB, 8): z&1 -> input select, z>>1 -> ci quarter.
__global__ void __launch_bounds__(256)
colmax8(const float* __restrict__ Xq, const float* __restrict__ Xk,
        float* __restrict__ sXq, float* __restrict__ sXk)
{
    const int n = blockIdx.x * 256 + threadIdx.x;
    const int b = blockIdx.y;
    const int zz = blockIdx.z;
    const float* X = (zz & 1) ? Xk : Xq;
    float* sX = (zz & 1) ? sXk : sXq;
    const int c0 = (zz >> 1) * (CIN / 4);
    const float* p = X + (size_t)b * CIN * NPIX + (size_t)c0 * NPIX + n;
    float m = 0.f;
    for (int ci = 0; ci < CIN / 4; ci++) m = fmaxf(m, fabsf(p[(size_t)ci * NPIX]));
    atomicMax((int*)&sX[b * NPIX + n], __float_as_int(m * (1.f / 127.f)));
}

// Merged transpose + quantize for both inputs: grid (NPIX/32, CIN/32, 2*NB)
__global__ void __launch_bounds__(256)
transpose_quant2(const float* __restrict__ Xq, const float* __restrict__ Xk,
                 const float* __restrict__ sXq, const float* __restrict__ sXk,
                 int8_t* __restrict__ Xq2, int8_t* __restrict__ Xk2)
{
    __shared__ float t[32][33];
    const int zz = blockIdx.z;
    const int b = zz & (NB - 1);
    const int which = zz >> 2;
    const float* X = which ? Xk : Xq;
    const float* sX = which ? sXk : sXq;
    int8_t* X2 = which ? Xk2 : Xq2;

    const int n0 = blockIdx.x * 32, c0 = blockIdx.y * 32;
    const int tx = threadIdx.x & 31, ty = threadIdx.x >> 5;
    const float* Xb = X + (size_t)b * CIN * NPIX;
    #pragma unroll
    for (int r = 0; r < 4; r++)
        t[ty + r * 8][tx] = Xb[(size_t)(c0 + ty + r * 8) * NPIX + n0 + tx];
    __syncthreads();
    const size_t ob = (size_t)b * NPIX * 2 * CIN;
    #pragma unroll
    for (int r = 0; r < 4; r++) {
        const int n = n0 + ty + r * 8;
        const int c = c0 + tx;
        const float v = t[tx][ty + r * 8];
        const float s1 = sX[b * NPIX + n];
        const float i1 = (s1 > 0.f) ? (1.f / s1) : 0.f;
        float q1 = clamp127(rintf(v * i1));
        float rr = v - q1 * s1;
        float q2 = clamp127(rintf(rr * i1 * 252.f));
        const size_t row = ob + (size_t)n * (2 * CIN);
        X2[row + c] = (int8_t)(int)q1;
        X2[row + CIN + c] = (int8_t)(int)q2;
    }
}

// -------- softmax: int16 S rows -> int8 attn [q1|q2] + scale ---------------
__global__ void __launch_bounds__(256)
softmax2_q(const int16_t* __restrict__ S, int8_t* __restrict__ A2,
           float* __restrict__ sAt)
{
    const size_t rb = (size_t)blockIdx.x * NPIX;
    const int16_t* row = S + rb;
    int8_t* orow = A2 + (size_t)blockIdx.x * (2 * NPIX);
    const int t = threadIdx.x;
    float v[16];
    float m = -1e30f;
    #pragma unroll
    for (int i = 0; i < 16; i++) {
        v[i] = (float)row[t + i * 256] * INVSSCALE;
        m = fmaxf(m, v[i]);
    }
    #pragma unroll
    for (int o = 16; o > 0; o >>= 1) m = fmaxf(m, __shfl_xor_sync(~0u, m, o));
    __shared__ float smax[8], ssum[8];
    if ((t & 31) == 0) smax[t >> 5] = m;
    __syncthreads();
    float mm = smax[0];
    #pragma unroll
    for (int i = 1; i < 8; i++) mm = fmaxf(mm, smax[i]);
    float s = 0.f;
    #pragma unroll
    for (int i = 0; i < 16; i++) { v[i] = __expf(v[i] - mm); s += v[i]; }
    #pragma unroll
    for (int o = 16; o > 0; o >>= 1) s += __shfl_xor_sync(~0u, s, o);
    if ((t & 31) == 0) ssum[t >> 5] = s;
    __syncthreads();
    float tot = 0.f;
    #pragma unroll
    for (int i = 0; i < 8; i++) tot += ssum[i];
    const float inv = 1.0f / tot;

    #pragma unroll
    for (int i = 0; i < 16; i++) {
        const int k = t + i * 256;
        float f = v[i] * 127.f;
        float q1 = clamp127(rintf(f));
        float q2 = clamp127(rintf((f - q1) * 252.f));
        orow[k] = (int8_t)(int)q1;
        orow[NPIX + k] = (int8_t)(int)q2;
    }
    if (t == 0) sAt[blockIdx.x] = inv * (1.f / 127.f);
}

// ------------------------------- host -------------------------------------
extern "C" void kernel_launch(void* const* d_in, const int* in_sizes, int n_in,
                              void* d_out, int out_size)
{
    const float* qfeat = (const float*)d_in[0];
    const float* kfeat = (const float*)d_in[1];
    const float* Wq = (const float*)d_in[2];
    const float* bq = (const float*)d_in[3];
    const float* Wk = (const float*)d_in[4];
    const float* bk = (const float*)d_in[5];
    const float* Wv = (const float*)d_in[6];
    const float* bv = (const float*)d_in[7];
    float* out = (float*)d_out;

    void *Xq2, *Xk2, *Wq2, *Wk2, *Wv2, *Qf, *Kf, *Vf, *Q2, *K2, *V2, *Sd, *A2;
    void *sXq, *sXk, *sWq, *sWk, *sWv, *sQ, *sK, *sV, *sAt;
    cudaGetSymbolAddress(&Xq2, g_Xq2);
    cudaGetSymbolAddress(&Xk2, g_Xk2);
    cudaGetSymbolAddress(&Wq2, g_Wq2);
    cudaGetSymbolAddress(&Wk2, g_Wk2);
    cudaGetSymbolAddress(&Wv2, g_Wv2);
    cudaGetSymbolAddress(&Qf, g_Qf);
    cudaGetSymbolAddress(&Kf, g_Kf);
    cudaGetSymbolAddress(&Vf, g_Vf);
    cudaGetSymbolAddress(&Q2, g_Q2);
    cudaGetSymbolAddress(&K2, g_K2);
    cudaGetSymbolAddress(&V2, g_V2);
    cudaGetSymbolAddress(&Sd, g_S);
    cudaGetSymbolAddress(&A2, g_A2);
    cudaGetSymbolAddress(&sXq, g_sXq);
    cudaGetSymbolAddress(&sXk, g_sXk);
    cudaGetSymbolAddress(&sWq, g_sWq);
    cudaGetSymbolAddress(&sWk, g_sWk);
    cudaGetSymbolAddress(&sWv, g_sWv);
    cudaGetSymbolAddress(&sQ, g_sQ);
    cudaGetSymbolAddress(&sK, g_sK);
    cudaGetSymbolAddress(&sV, g_sV);
    cudaGetSymbolAddress(&sAt, g_sAt);

    cudaFuncSetAttribute(gemm_s8<0>, cudaFuncAttributeMaxDynamicSharedMemorySize, GSMEM);
    cudaFuncSetAttribute(gemm_s8<1>, cudaFuncAttributeMaxDynamicSharedMemorySize, GSMEM);

    // 1) weights quantization (merged)
    rowquantW<<<2 * CQK + COUT, 256>>>(Wq, Wk, Wv,
        (int8_t*)Wq2, (int8_t*)Wk2, (int8_t*)Wv2,
        (float*)sWq, (float*)sWk, (float*)sWv);

    // 2) column maxima (chunked + atomicMax)
    colmax8<<<dim3(NPIX / 256, NB, 8), 256>>>(qfeat, kfeat, (float*)sXq, (float*)sXk);

    // 3) transpose + quantize both inputs (merged)
    transpose_quant2<<<dim3(NPIX / 32, CIN / 32, 2 * NB), 256>>>(
        qfeat, kfeat, (const float*)sXq, (const float*)sXk,
        (int8_t*)Xq2, (int8_t*)Xk2);

    // 4) Q proj: Qf[b][n][c] = Xq2 . Wq2^T + bq  (M=4096, N=256, K=512)
    gemm_s8<0><<<dim3(CQK / 128, NPIX / 128, NB), 256, GSMEM>>>(
        (const int8_t*)Xq2, (size_t)NPIX * 2 * CIN,
        (const int8_t*)Wq2, 0, CIN,
        (float*)Qf, nullptr, (size_t)CQK, (size_t)NPIX * CQK,
        (const float*)sXq, (size_t)NPIX, (const float*)sWq, 0,
        nullptr, bq, 1.0f);

    // 5) K proj  <- profiled launch slot
    gemm_s8<0><<<dim3(CQK / 128, NPIX / 128, NB), 256, GSMEM>>>(
        (const int8_t*)Xk2, (size_t)NPIX * 2 * CIN,
        (const int8_t*)Wk2, 0, CIN,
        (float*)Kf, nullptr, (size_t)CQK, (size_t)NPIX * CQK,
        (const float*)sXk, (size_t)NPIX, (const float*)sWk, 0,
        nullptr, bk, 1.0f);

    // 6) V proj: Vf[b][o][m] = Wv2 . Xk2^T + bv  (M=512, N=4096, K=512)
    gemm_s8<0><<<dim3(NPIX / 128, COUT / 128, NB), 256, GSMEM>>>(
        (const int8_t*)Wv2, 0,
        (const int8_t*)Xk2, (size_t)NPIX * 2 * CIN, CIN,
        (float*)Vf, nullptr, (size_t)NPIX, (size_t)COUT * NPIX,
        (const float*)sWv, 0, (const float*)sXk, (size_t)NPIX,
        bv, nullptr, 1.0f);

    // 7) quantize Q+K (merged) and V
    rowquantQK<<<2 * NB * NPIX, 256>>>((const float*)Qf, (const float*)Kf,
        (int8_t*)Q2, (int8_t*)K2, (float*)sQ, (float*)sK);
    rowquantV<<<NB * COUT, 256>>>((const float*)Vf, (int8_t*)V2, (float*)sV);

    // 8) sim: S = int16( (1/16) Q2 . K2^T * SSCALE )  (M=N=4096, K=256)
    gemm_s8<1><<<dim3(NPIX / 128, NPIX / 128, NB), 256, GSMEM>>>(
        (const int8_t*)Q2, (size_t)NPIX * 2 * CQK,
        (const int8_t*)K2, (size_t)NPIX * 2 * CQK, CQK,
        nullptr, (int16_t*)Sd, (size_t)NPIX, (size_t)NPIX * NPIX,
        (const float*)sQ, (size_t)NPIX, (const float*)sK, (size_t)NPIX,
        nullptr, nullptr, 0.0625f);

    // 9) softmax -> int8 attn [q1|q2] + scales
    softmax2_q<<<NB * NPIX, 256>>>((const int16_t*)Sd, (int8_t*)A2, (float*)sAt);

    // 10) ctx: out = V2 . A2^T  (M=512, N=4096, K=4096)
    gemm_s8<0><<<dim3(NPIX / 128, COUT / 128, NB), 256, GSMEM>>>(
        (const int8_t*)V2, (size_t)COUT * 2 * NPIX,
        (const int8_t*)A2, (size_t)NPIX * 2 * NPIX, NPIX,
        out, nullptr, (size_t)NPIX, (size_t)COUT * NPIX,
        (const float*)sV, (size_t)COUT, (const float*)sAt, (size_t)NPIX,
        nullptr, nullptr, 1.0f);
}

// round 13
// speedup vs baseline: 3.2352x; 1.0772x over previous
#include <cuda_runtime.h>
#include <cstdint>
#include <cstddef>

#define NB    4
#define CIN   512
#define NPIX  4096
#define CQK   256
#define COUT  512

// GEMM tiling: block 128(M)x64(N), K-chunk 128 int8 bytes, 3-stage cp.async,
// 8 warps as 4(M)x2(N), warp tile 32x32, 2 CTAs/SM.
#define ROWB    144           // padded smem row bytes (128B data + 16B pad)
#define STAGE_SZ ((128+64)*ROWB) // 27648 B
#define NSTAGE  3
#define GSMEM   (STAGE_SZ*NSTAGE)   // 82944 B -> 2 CTAs/SM
#define INV252  (1.0f/252.0f)
#define SSCALE  2048.0f
#define INVSSCALE (1.0f/2048.0f)

// -------------------- scratch (device globals) ----------------------------
__device__ int8_t  g_Xq2[(size_t)NB*NPIX*2*CIN];
__device__ int8_t  g_Xk2[(size_t)NB*NPIX*2*CIN];
__device__ int8_t  g_Wq2[CQK*2*CIN];
__device__ int8_t  g_Wk2[CQK*2*CIN];
__device__ int8_t  g_Wv2[COUT*2*CIN];
__device__ float   g_Qf[(size_t)NB*NPIX*CQK];
__device__ float   g_Kf[(size_t)NB*NPIX*CQK];
__device__ float   g_Vf[(size_t)NB*COUT*NPIX];
__device__ int8_t  g_Q2[(size_t)NB*NPIX*2*CQK];
__device__ int8_t  g_K2[(size_t)NB*NPIX*2*CQK];
__device__ int8_t  g_V2[(size_t)NB*COUT*2*NPIX];
__device__ int16_t g_S [(size_t)NB*NPIX*NPIX];
__device__ int8_t  g_A2[(size_t)NB*NPIX*2*NPIX];
__device__ float g_sXq[NB*NPIX], g_sXk[NB*NPIX];
__device__ float g_sWq[CQK], g_sWk[CQK], g_sWv[COUT];
__device__ float g_sQ[NB*NPIX], g_sK[NB*NPIX], g_sV[NB*COUT], g_sAt[NB*NPIX];

// -------------------- PTX helpers -----------------------------------------
__device__ __forceinline__ uint32_t s2u(const void* p) {
    uint32_t a;
    asm("{ .reg .u64 t; cvta.to.shared.u64 t, %1; cvt.u32.u64 %0, t; }" : "=r"(a) : "l"(p));
    return a;
}
__device__ __forceinline__ void cp16(uint32_t s, const void* g) {
    asm volatile("cp.async.cg.shared.global [%0], [%1], 16;" :: "r"(s), "l"(g));
}
#define CP_COMMIT() asm volatile("cp.async.commit_group;" ::: "memory")
#define CP_WAIT1()  asm volatile("cp.async.wait_group 1;" ::: "memory")

__device__ __forceinline__ void ldm4(uint32_t& r0, uint32_t& r1, uint32_t& r2, uint32_t& r3,
                                     uint32_t a) {
    asm volatile("ldmatrix.sync.aligned.m8n8.x4.shared.b16 {%0,%1,%2,%3}, [%4];"
                 : "=r"(r0), "=r"(r1), "=r"(r2), "=r"(r3) : "r"(a));
}
__device__ __forceinline__ void mma16832(int* d, const uint32_t* a, uint32_t b0, uint32_t b1) {
    asm volatile(
      "mma.sync.aligned.m16n8k32.row.col.s32.s8.s8.s32 "
      "{%0,%1,%2,%3},{%4,%5,%6,%7},{%8,%9},{%0,%1,%2,%3};"
      : "+r"(d[0]), "+r"(d[1]), "+r"(d[2]), "+r"(d[3])
      : "r"(a[0]), "r"(a[1]), "r"(a[2]), "r"(a[3]), "r"(b0), "r"(b1));
}

// -------------------- canonical int8 Ozaki GEMM ---------------------------
// D[M,N] = scale * sigA[m]*sigB[n]*(acc0 + acc1/252) + bias_row[m] + bias_col[n]
// Physical rows [q1|q2] (2K bytes). Logical 128B chunks: A [q1|q1|q2],
// B [q1|q2|q1] via remap; chunks < K/128 -> acc0, rest -> acc1.
// EPI 0: fp32 out.  EPI 1: int16 out (value * SSCALE, clamped).
template<int EPI>
__global__ void __launch_bounds__(256, 2)
gemm_s8(const int8_t* __restrict__ A, size_t sA,
        const int8_t* __restrict__ B, size_t sB,
        int K,
        float* __restrict__ Cf, int16_t* __restrict__ Cs, size_t ldc, size_t sC,
        const float* __restrict__ sAarr, size_t sAstr,
        const float* __restrict__ sBarr, size_t sBstr,
        const float* __restrict__ bias_row, const float* __restrict__ bias_col,
        float scale)
{
    extern __shared__ __align__(128) char smem[];
    const uint32_t sb = s2u(smem);
    const int tid = threadIdx.x, lane = tid & 31, wid = tid >> 5;
    const int wm0 = (wid & 3) * 32;      // 4 warps along M
    const int wn0 = (wid >> 2) * 32;     // 2 warps along N
    const int m0 = blockIdx.y * 128, n0 = blockIdx.x * 64, z = blockIdx.z;

    const int n1 = K / 128;
    const int nk = 3 * n1;
    const int rowlen = 2 * K;

    A += (size_t)z * sA + (size_t)m0 * rowlen;
    B += (size_t)z * sB + (size_t)n0 * rowlen;

    auto load_stage = [&](int st, int kc) {
        const int ca = (kc < n1) ? kc : kc - n1;          // A: [q1|q1|q2]
        const int cb = (kc < 2 * n1) ? kc : kc - 2 * n1;  // B: [q1|q2|q1]
        const int8_t* ga = A + (size_t)ca * 128;
        const int8_t* gb = B + (size_t)cb * 128;
        uint32_t sa = sb + st * STAGE_SZ;
        uint32_t sbm = sa + 128 * ROWB;
        #pragma unroll
        for (int i = 0; i < 6; i++) {
            const int idx = tid + i * 256;     // 0..1535 over 192 rows x 8 chunks
            const int row = idx >> 3, ch = idx & 7;
            if (row < 128)
                cp16(sa + row * ROWB + ch * 16, ga + (size_t)row * rowlen + ch * 16);
            else
                cp16(sbm + (row - 128) * ROWB + ch * 16,
                     gb + (size_t)(row - 128) * rowlen + ch * 16);
        }
    };

    int acc0[2][4][4], acc1[2][4][4];
    #pragma unroll
    for (int i = 0; i < 2; i++)
        #pragma unroll
        for (int j = 0; j < 4; j++)
            #pragma unroll
            for (int q = 0; q < 4; q++) { acc0[i][j][q] = 0; acc1[i][j][q] = 0; }

    load_stage(0, 0); CP_COMMIT();
    load_stage(1, 1); CP_COMMIT();

    const int arow = wm0 + (lane & 15);
    const int acsel = (lane >> 4);
    const int brow = wn0 + (lane & 7) + ((lane >> 4) & 1) * 8;
    const int bcsel = (lane >> 3) & 1;

    for (int k = 0; k < nk; k++) {
        CP_WAIT1();
        __syncthreads();
        if (k + 2 < nk) load_stage((k + 2) % NSTAGE, k + 2);
        CP_COMMIT();

        const uint32_t sa = sb + (k % NSTAGE) * STAGE_SZ;
        const uint32_t sbm = sa + 128 * ROWB;

        #pragma unroll
        for (int ks = 0; ks < 4; ks++) {
            uint32_t a[2][4], bfr[2][4];
            const uint32_t ac = (ks * 2 + acsel) * 16;
            #pragma unroll
            for (int i = 0; i < 2; i++)
                ldm4(a[i][0], a[i][1], a[i][2], a[i][3],
                     sa + (arow + i * 16) * ROWB + ac);
            const uint32_t bc = (ks * 2 + bcsel) * 16;
            #pragma unroll
            for (int j = 0; j < 2; j++)
                ldm4(bfr[j][0], bfr[j][1], bfr[j][2], bfr[j][3],
                     sbm + (brow + j * 16) * ROWB + bc);
            if (k < n1) {
                #pragma unroll
                for (int i = 0; i < 2; i++)
                    #pragma unroll
                    for (int jn = 0; jn < 4; jn++)
                        mma16832(acc0[i][jn], a[i],
                                 bfr[jn >> 1][(jn & 1) * 2], bfr[jn >> 1][(jn & 1) * 2 + 1]);
            } else {
                #pragma unroll
                for (int i = 0; i < 2; i++)
                    #pragma unroll
                    for (int jn = 0; jn < 4; jn++)
                        mma16832(acc1[i][jn], a[i],
                                 bfr[jn >> 1][(jn & 1) * 2], bfr[jn >> 1][(jn & 1) * 2 + 1]);
            }
        }
        __syncthreads();
    }

    // -------- epilogue --------
    const int mb = m0 + wm0 + (lane >> 2);
    const int nb = n0 + wn0 + (lane & 3) * 2;
    #pragma unroll
    for (int i = 0; i < 2; i++) {
        #pragma unroll
        for (int half = 0; half < 2; half++) {
            const int m = mb + i * 16 + half * 8;
            const float sAm = sAarr[z * sAstr + m] * scale;
            const float br = bias_row ? bias_row[m] : 0.f;
            #pragma unroll
            for (int jn = 0; jn < 4; jn++) {
                const int n = nb + jn * 8;
                float f0 = (float)acc0[i][jn][half * 2 + 0]
                         + (float)acc1[i][jn][half * 2 + 0] * INV252;
                float f1 = (float)acc0[i][jn][half * 2 + 1]
                         + (float)acc1[i][jn][half * 2 + 1] * INV252;
                float v0 = f0 * sAm * sBarr[z * sBstr + n] + br;
                float v1 = f1 * sAm * sBarr[z * sBstr + n + 1] + br;
                if (bias_col) { v0 += bias_col[n]; v1 += bias_col[n + 1]; }
                if (EPI == 0) {
                    *(float2*)&Cf[(size_t)z * sC + (size_t)m * ldc + n] = make_float2(v0, v1);
                } else {
                    float q0 = fminf(fmaxf(v0 * SSCALE, -32000.f), 32000.f);
                    float q1 = fminf(fmaxf(v1 * SSCALE, -32000.f), 32000.f);
                    short2 o;
                    o.x = (short)(int)rintf(q0);
                    o.y = (short)(int)rintf(q1);
                    *(short2*)&Cs[(size_t)z * sC + (size_t)m * ldc + n] = o;
                }
            }
        }
    }
}

// -------------------- quantization helpers --------------------------------
__device__ __forceinline__ float clamp127(float q) {
    return fminf(127.f, fmaxf(-127.f, q));
}

__device__ __forceinline__ void rowquant_body(const float* __restrict__ src, int len,
                                              int8_t* __restrict__ dst,
                                              float* __restrict__ sOut)
{
    const int t = threadIdx.x;
    float m = 0.f;
    for (int i = t; i < len; i += 256) m = fmaxf(m, fabsf(src[i]));
    #pragma unroll
    for (int o = 16; o > 0; o >>= 1) m = fmaxf(m, __shfl_xor_sync(~0u, m, o));
    __shared__ float sm[8];
    if ((t & 31) == 0) sm[t >> 5] = m;
    __syncthreads();
    float mm = sm[0];
    #pragma unroll
    for (int i = 1; i < 8; i++) mm = fmaxf(mm, sm[i]);

    const float s1 = mm * (1.f / 127.f);
    const float i1 = (mm > 0.f) ? (127.f / mm) : 0.f;
    const float i2 = i1 * 252.f;

    for (int i = t; i < len; i += 256) {
        float x = src[i];
        float q1 = clamp127(rintf(x * i1));
        float r = x - q1 * s1;
        float q2 = clamp127(rintf(r * i2));
        dst[i] = (int8_t)(int)q1;
        dst[len + i] = (int8_t)(int)q2;
    }
    if (t == 0) *sOut = s1;
}

__global__ void __launch_bounds__(256)
rowquantW(const float* __restrict__ Wq, const float* __restrict__ Wk,
          const float* __restrict__ Wv,
          int8_t* __restrict__ Wq2, int8_t* __restrict__ Wk2, int8_t* __restrict__ Wv2,
          float* __restrict__ sWq, float* __restrict__ sWk, float* __restrict__ sWv)
{
    const int r = blockIdx.x;
    const float* src; int8_t* dst; float* sOut;
    if (r < CQK)            { src = Wq + (size_t)r * CIN;          dst = Wq2 + (size_t)r * 2 * CIN;          sOut = sWq + r; }
    else if (r < 2 * CQK)   { int rr = r - CQK;   src = Wk + (size_t)rr * CIN; dst = Wk2 + (size_t)rr * 2 * CIN; sOut = sWk + rr; }
    else                    { int rr = r - 2*CQK; src = Wv + (size_t)rr * CIN; dst = Wv2 + (size_t)rr * 2 * CIN; sOut = sWv + rr; }
    rowquant_body(src, CIN, dst, sOut);
}

__global__ void __launch_bounds__(256)
rowquantQK(const float* __restrict__ Qf, const float* __restrict__ Kf,
           int8_t* __restrict__ Q2, int8_t* __restrict__ K2,
           float* __restrict__ sQ, float* __restrict__ sK)
{
    const size_t r = blockIdx.x;
    const size_t nrows = (size_t)NB * NPIX;
    if (r < nrows)
        rowquant_body(Qf + r * CQK, CQK, Q2 + r * 2 * CQK, sQ + r);
    else {
        const size_t rr = r - nrows;
        rowquant_body(Kf + rr * CQK, CQK, K2 + rr * 2 * CQK, sK + rr);
    }
}

__global__ void __launch_bounds__(256)
rowquantV(const float* __restrict__ Vf, int8_t* __restrict__ V2, float* __restrict__ sV)
{
    const size_t r = blockIdx.x;
    rowquant_body(Vf + r * NPIX, NPIX, V2 + r * 2 * NPIX, sV + r);
}

// Chunked column-max with atomicMax (non-negative floats as ints: monotone;
// deterministic across graph replays). grid (NPIX/256, NB, 8).
__global__ void __launch_bounds__(256)
colmax8(const float* __restrict__ Xq, const float* __restrict__ Xk,
        float* __restrict__ sXq, float* __restrict__ sXk)
{
    const int n = blockIdx.x * 256 + threadIdx.x;
    const int b = blockIdx.y;
    const int zz = blockIdx.z;
    const float* X = (zz & 1) ? Xk : Xq;
    float* sX = (zz & 1) ? sXk : sXq;
    const int c0 = (zz >> 1) * (CIN / 4);
    const float* p = X + (size_t)b * CIN * NPIX + (size_t)c0 * NPIX + n;
    float m = 0.f;
    for (int ci = 0; ci < CIN / 4; ci++) m = fmaxf(m, fabsf(p[(size_t)ci * NPIX]));
    atomicMax((int*)&sX[b * NPIX + n], __float_as_int(m * (1.f / 127.f)));
}

// Merged transpose + quantize for both inputs: grid (NPIX/32, CIN/32, 2*NB)
__global__ void __launch_bounds__(256)
transpose_quant2(const float* __restrict__ Xq, const float* __restrict__ Xk,
                 const float* __restrict__ sXq, const float* __restrict__ sXk,
                 int8_t* __restrict__ Xq2, int8_t* __restrict__ Xk2)
{
    __shared__ float t[32][33];
    const int zz = blockIdx.z;
    const int b = zz & (NB - 1);
    const int which = zz >> 2;
    const float* X = which ? Xk : Xq;
    const float* sX = which ? sXk : sXq;
    int8_t* X2 = which ? Xk2 : Xq2;

    const int n0 = blockIdx.x * 32, c0 = blockIdx.y * 32;
    const int tx = threadIdx.x & 31, ty = threadIdx.x >> 5;
    const float* Xb = X + (size_t)b * CIN * NPIX;
    #pragma unroll
    for (int r = 0; r < 4; r++)
        t[ty + r * 8][tx] = Xb[(size_t)(c0 + ty + r * 8) * NPIX + n0 + tx];
    __syncthreads();
    const size_t ob = (size_t)b * NPIX * 2 * CIN;
    #pragma unroll
    for (int r = 0; r < 4; r++) {
        const int n = n0 + ty + r * 8;
        const int c = c0 + tx;
        const float v = t[tx][ty + r * 8];
        const float s1 = sX[b * NPIX + n];
        const float i1 = (s1 > 0.f) ? (1.f / s1) : 0.f;
        float q1 = clamp127(rintf(v * i1));
        float rr = v - q1 * s1;
        float q2 = clamp127(rintf(rr * i1 * 252.f));
        const size_t row = ob + (size_t)n * (2 * CIN);
        X2[row + c] = (int8_t)(int)q1;
        X2[row + CIN + c] = (int8_t)(int)q2;
    }
}

// -------- softmax: int16 S rows -> int8 attn [q1|q2] + scale ---------------
__global__ void __launch_bounds__(256)
softmax2_q(const int16_t* __restrict__ S, int8_t* __restrict__ A2,
           float* __restrict__ sAt)
{
    const size_t rb = (size_t)blockIdx.x * NPIX;
    const int16_t* row = S + rb;
    int8_t* orow = A2 + (size_t)blockIdx.x * (2 * NPIX);
    const int t = threadIdx.x;
    float v[16];
    float m = -1e30f;
    #pragma unroll
    for (int i = 0; i < 16; i++) {
        v[i] = (float)row[t + i * 256] * INVSSCALE;
        m = fmaxf(m, v[i]);
    }
    #pragma unroll
    for (int o = 16; o > 0; o >>= 1) m = fmaxf(m, __shfl_xor_sync(~0u, m, o));
    __shared__ float smax[8], ssum[8];
    if ((t & 31) == 0) smax[t >> 5] = m;
    __syncthreads();
    float mm = smax[0];
    #pragma unroll
    for (int i = 1; i < 8; i++) mm = fmaxf(mm, smax[i]);
    float s = 0.f;
    #pragma unroll
    for (int i = 0; i < 16; i++) { v[i] = __expf(v[i] - mm); s += v[i]; }
    #pragma unroll
    for (int o = 16; o > 0; o >>= 1) s += __shfl_xor_sync(~0u, s, o);
    if ((t & 31) == 0) ssum[t >> 5] = s;
    __syncthreads();
    float tot = 0.f;
    #pragma unroll
    for (int i = 0; i < 8; i++) tot += ssum[i];
    const float inv = 1.0f / tot;

    #pragma unroll
    for (int i = 0; i < 16; i++) {
        const int k = t + i * 256;
        float f = v[i] * 127.f;
        float q1 = clamp127(rintf(f));
        float q2 = clamp127(rintf((f - q1) * 252.f));
        orow[k] = (int8_t)(int)q1;
        orow[NPIX + k] = (int8_t)(int)q2;
    }
    if (t == 0) sAt[blockIdx.x] = inv * (1.f / 127.f);
}

// ------------------------------- host -------------------------------------
extern "C" void kernel_launch(void* const* d_in, const int* in_sizes, int n_in,
                              void* d_out, int out_size)
{
    const float* qfeat = (const float*)d_in[0];
    const float* kfeat = (const float*)d_in[1];
    const float* Wq = (const float*)d_in[2];
    const float* bq = (const float*)d_in[3];
    const float* Wk = (const float*)d_in[4];
    const float* bk = (const float*)d_in[5];
    const float* Wv = (const float*)d_in[6];
    const float* bv = (const float*)d_in[7];
    float* out = (float*)d_out;

    void *Xq2, *Xk2, *Wq2, *Wk2, *Wv2, *Qf, *Kf, *Vf, *Q2, *K2, *V2, *Sd, *A2;
    void *sXq, *sXk, *sWq, *sWk, *sWv, *sQ, *sK, *sV, *sAt;
    cudaGetSymbolAddress(&Xq2, g_Xq2);
    cudaGetSymbolAddress(&Xk2, g_Xk2);
    cudaGetSymbolAddress(&Wq2, g_Wq2);
    cudaGetSymbolAddress(&Wk2, g_Wk2);
    cudaGetSymbolAddress(&Wv2, g_Wv2);
    cudaGetSymbolAddress(&Qf, g_Qf);
    cudaGetSymbolAddress(&Kf, g_Kf);
    cudaGetSymbolAddress(&Vf, g_Vf);
    cudaGetSymbolAddress(&Q2, g_Q2);
    cudaGetSymbolAddress(&K2, g_K2);
    cudaGetSymbolAddress(&V2, g_V2);
    cudaGetSymbolAddress(&Sd, g_S);
    cudaGetSymbolAddress(&A2, g_A2);
    cudaGetSymbolAddress(&sXq, g_sXq);
    cudaGetSymbolAddress(&sXk, g_sXk);
    cudaGetSymbolAddress(&sWq, g_sWq);
    cudaGetSymbolAddress(&sWk, g_sWk);
    cudaGetSymbolAddress(&sWv, g_sWv);
    cudaGetSymbolAddress(&sQ, g_sQ);
    cudaGetSymbolAddress(&sK, g_sK);
    cudaGetSymbolAddress(&sV, g_sV);
    cudaGetSymbolAddress(&sAt, g_sAt);

    cudaFuncSetAttribute(gemm_s8<0>, cudaFuncAttributeMaxDynamicSharedMemorySize, GSMEM);
    cudaFuncSetAttribute(gemm_s8<1>, cudaFuncAttributeMaxDynamicSharedMemorySize, GSMEM);

    // 1) weights quantization (merged)
    rowquantW<<<2 * CQK + COUT, 256>>>(Wq, Wk, Wv,
        (int8_t*)Wq2, (int8_t*)Wk2, (int8_t*)Wv2,
        (float*)sWq, (float*)sWk, (float*)sWv);

    // 2) column maxima (chunked + atomicMax)
    colmax8<<<dim3(NPIX / 256, NB, 8), 256>>>(qfeat, kfeat, (float*)sXq, (float*)sXk);

    // 3) transpose + quantize both inputs (merged)
    transpose_quant2<<<dim3(NPIX / 32, CIN / 32, 2 * NB), 256>>>(
        qfeat, kfeat, (const float*)sXq, (const float*)sXk,
        (int8_t*)Xq2, (int8_t*)Xk2);

    // 4) Q proj: Qf[b][n][c] = Xq2 . Wq2^T + bq  (M=4096, N=256, K=512)
    gemm_s8<0><<<dim3(CQK / 64, NPIX / 128, NB), 256, GSMEM>>>(
        (const int8_t*)Xq2, (size_t)NPIX * 2 * CIN,
        (const int8_t*)Wq2, 0, CIN,
        (float*)Qf, nullptr, (size_t)CQK, (size_t)NPIX * CQK,
        (const float*)sXq, (size_t)NPIX, (const float*)sWq, 0,
        nullptr, bq, 1.0f);

    // 5) K proj  <- profiled launch slot
    gemm_s8<0><<<dim3(CQK / 64, NPIX / 128, NB), 256, GSMEM>>>(
        (const int8_t*)Xk2, (size_t)NPIX * 2 * CIN,
        (const int8_t*)Wk2, 0, CIN,
        (float*)Kf, nullptr, (size_t)CQK, (size_t)NPIX * CQK,
        (const float*)sXk, (size_t)NPIX, (const float*)sWk, 0,
        nullptr, bk, 1.0f);

    // 6) V proj: Vf[b][o][m] = Wv2 . Xk2^T + bv  (M=512, N=4096, K=512)
    gemm_s8<0><<<dim3(NPIX / 64, COUT / 128, NB), 256, GSMEM>>>(
        (const int8_t*)Wv2, 0,
        (const int8_t*)Xk2, (size_t)NPIX * 2 * CIN, CIN,
        (float*)Vf, nullptr, (size_t)NPIX, (size_t)COUT * NPIX,
        (const float*)sWv, 0, (const float*)sXk, (size_t)NPIX,
        bv, nullptr, 1.0f);

    // 7) quantize Q+K (merged) and V
    rowquantQK<<<2 * NB * NPIX, 256>>>((const float*)Qf, (const float*)Kf,
        (int8_t*)Q2, (int8_t*)K2, (float*)sQ, (float*)sK);
    rowquantV<<<NB * COUT, 256>>>((const float*)Vf, (int8_t*)V2, (float*)sV);

    // 8) sim: S = int16( (1/16) Q2 . K2^T * SSCALE )  (M=N=4096, K=256)
    gemm_s8<1><<<dim3(NPIX / 64, NPIX / 128, NB), 256, GSMEM>>>(
        (const int8_t*)Q2, (size_t)NPIX * 2 * CQK,
        (const int8_t*)K2, (size_t)NPIX * 2 * CQK, CQK,
        nullptr, (int16_t*)Sd, (size_t)NPIX, (size_t)NPIX * NPIX,
        (const float*)sQ, (size_t)NPIX, (const float*)sK, (size_t)NPIX,
        nullptr, nullptr, 0.0625f);

    // 9) softmax -> int8 attn [q1|q2] + scales
    softmax2_q<<<NB * NPIX, 256>>>((const int16_t*)Sd, (int8_t*)A2, (float*)sAt);

    // 10) ctx: out = V2 . A2^T  (M=512, N=4096, K=4096)
    gemm_s8<0><<<dim3(NPIX / 64, COUT / 128, NB), 256, GSMEM>>>(
        (const int8_t*)V2, (size_t)COUT * 2 * NPIX,
        (const int8_t*)A2, (size_t)NPIX * 2 * NPIX, NPIX,
        out, nullptr, (size_t)NPIX, (size_t)COUT * NPIX,
        (const float*)sV, (size_t)COUT, (const float*)sAt, (size_t)NPIX,
        nullptr, nullptr, 1.0f);
}

// round 14
// speedup vs baseline: 3.2933x; 1.0180x over previous
#include <cuda_runtime.h>
#include <cstdint>
#include <cstddef>

#define NB    4
#define CIN   512
#define NPIX  4096
#define CQK   256
#define COUT  512

// GEMM tiling: block 128(M)x64(N), K-chunk 128 int8 bytes, 4-stage cp.async,
// prefetch distance 3, ONE barrier per chunk. 8 warps 4(M)x2(N), warp 32x32,
// 2 CTAs/SM (2 x 110.6 KB smem = 221 KB <= 228 KB/SM; cp.async.cg bypasses L1).
#define ROWB    144           // padded smem row bytes (128B data + 16B pad)
#define STAGE_SZ ((128+64)*ROWB) // 27648 B
#define NSTAGE  4
#define GSMEM   (STAGE_SZ*NSTAGE)   // 110592 B
#define INV252  (1.0f/252.0f)
#define SSCALE  2048.0f
#define INVSSCALE (1.0f/2048.0f)

// -------------------- scratch (device globals) ----------------------------
__device__ int8_t  g_Xq2[(size_t)NB*NPIX*2*CIN];
__device__ int8_t  g_Xk2[(size_t)NB*NPIX*2*CIN];
__device__ int8_t  g_Wq2[CQK*2*CIN];
__device__ int8_t  g_Wk2[CQK*2*CIN];
__device__ int8_t  g_Wv2[COUT*2*CIN];
__device__ float   g_Qf[(size_t)NB*NPIX*CQK];
__device__ float   g_Kf[(size_t)NB*NPIX*CQK];
__device__ float   g_Vf[(size_t)NB*COUT*NPIX];
__device__ int8_t  g_Q2[(size_t)NB*NPIX*2*CQK];
__device__ int8_t  g_K2[(size_t)NB*NPIX*2*CQK];
__device__ int8_t  g_V2[(size_t)NB*COUT*2*NPIX];
__device__ int16_t g_S [(size_t)NB*NPIX*NPIX];
__device__ int8_t  g_A2[(size_t)NB*NPIX*2*NPIX];
__device__ float g_sXq[NB*NPIX], g_sXk[NB*NPIX];
__device__ float g_sWq[CQK], g_sWk[CQK], g_sWv[COUT];
__device__ float g_sQ[NB*NPIX], g_sK[NB*NPIX], g_sV[NB*COUT], g_sAt[NB*NPIX];

// -------------------- PTX helpers -----------------------------------------
__device__ __forceinline__ uint32_t s2u(const void* p) {
    uint32_t a;
    asm("{ .reg .u64 t; cvta.to.shared.u64 t, %1; cvt.u32.u64 %0, t; }" : "=r"(a) : "l"(p));
    return a;
}
__device__ __forceinline__ void cp16(uint32_t s, const void* g) {
    asm volatile("cp.async.cg.shared.global [%0], [%1], 16;" :: "r"(s), "l"(g));
}
#define CP_COMMIT() asm volatile("cp.async.commit_group;" ::: "memory")
#define CP_WAIT2()  asm volatile("cp.async.wait_group 2;" ::: "memory")

__device__ __forceinline__ void ldm4(uint32_t& r0, uint32_t& r1, uint32_t& r2, uint32_t& r3,
                                     uint32_t a) {
    asm volatile("ldmatrix.sync.aligned.m8n8.x4.shared.b16 {%0,%1,%2,%3}, [%4];"
                 : "=r"(r0), "=r"(r1), "=r"(r2), "=r"(r3) : "r"(a));
}
__device__ __forceinline__ void mma16832(int* d, const uint32_t* a, uint32_t b0, uint32_t b1) {
    asm volatile(
      "mma.sync.aligned.m16n8k32.row.col.s32.s8.s8.s32 "
      "{%0,%1,%2,%3},{%4,%5,%6,%7},{%8,%9},{%0,%1,%2,%3};"
      : "+r"(d[0]), "+r"(d[1]), "+r"(d[2]), "+r"(d[3])
      : "r"(a[0]), "r"(a[1]), "r"(a[2]), "r"(a[3]), "r"(b0), "r"(b1));
}

// -------------------- canonical int8 Ozaki GEMM ---------------------------
// D[M,N] = scale * sigA[m]*sigB[n]*(acc0 + acc1/252) + bias_row[m] + bias_col[n]
// Physical rows [q1|q2] (2K bytes). Logical 128B chunks: A [q1|q1|q2],
// B [q1|q2|q1] via remap; chunks < K/128 -> acc0, rest -> acc1.
// EPI 0: fp32 out.  EPI 1: int16 out (value * SSCALE, clamped).
template<int EPI>
__global__ void __launch_bounds__(256, 2)
gemm_s8(const int8_t* __restrict__ A, size_t sA,
        const int8_t* __restrict__ B, size_t sB,
        int K,
        float* __restrict__ Cf, int16_t* __restrict__ Cs, size_t ldc, size_t sC,
        const float* __restrict__ sAarr, size_t sAstr,
        const float* __restrict__ sBarr, size_t sBstr,
        const float* __restrict__ bias_row, const float* __restrict__ bias_col,
        float scale)
{
    extern __shared__ __align__(128) char smem[];
    const uint32_t sb = s2u(smem);
    const int tid = threadIdx.x, lane = tid & 31, wid = tid >> 5;
    const int wm0 = (wid & 3) * 32;      // 4 warps along M
    const int wn0 = (wid >> 2) * 32;     // 2 warps along N
    const int m0 = blockIdx.y * 128, n0 = blockIdx.x * 64, z = blockIdx.z;

    const int n1 = K / 128;
    const int nk = 3 * n1;          // >= 6 for all our K
    const int rowlen = 2 * K;

    A += (size_t)z * sA + (size_t)m0 * rowlen;
    B += (size_t)z * sB + (size_t)n0 * rowlen;

    auto load_stage = [&](int st, int kc) {
        const int ca = (kc < n1) ? kc : kc - n1;          // A: [q1|q1|q2]
        const int cb = (kc < 2 * n1) ? kc : kc - 2 * n1;  // B: [q1|q2|q1]
        const int8_t* ga = A + (size_t)ca * 128;
        const int8_t* gb = B + (size_t)cb * 128;
        uint32_t sa = sb + st * STAGE_SZ;
        uint32_t sbm = sa + 128 * ROWB;
        #pragma unroll
        for (int i = 0; i < 6; i++) {
            const int idx = tid + i * 256;     // 0..1535 over 192 rows x 8 chunks
            const int row = idx >> 3, ch = idx & 7;
            if (row < 128)
                cp16(sa + row * ROWB + ch * 16, ga + (size_t)row * rowlen + ch * 16);
            else
                cp16(sbm + (row - 128) * ROWB + ch * 16,
                     gb + (size_t)(row - 128) * rowlen + ch * 16);
        }
    };

    int acc0[2][4][4], acc1[2][4][4];
    #pragma unroll
    for (int i = 0; i < 2; i++)
        #pragma unroll
        for (int j = 0; j < 4; j++)
            #pragma unroll
            for (int q = 0; q < 4; q++) { acc0[i][j][q] = 0; acc1[i][j][q] = 0; }

    load_stage(0, 0); CP_COMMIT();
    load_stage(1, 1); CP_COMMIT();
    load_stage(2, 2); CP_COMMIT();

    const int arow = wm0 + (lane & 15);
    const int acsel = (lane >> 4);
    const int brow = wn0 + (lane & 7) + ((lane >> 4) & 1) * 8;
    const int bcsel = (lane >> 3) & 1;

    for (int k = 0; k < nk; k++) {
        // wait_group 2: chunks <= k complete (k+1, k+2 may be in flight)
        CP_WAIT2();
        __syncthreads();   // single barrier: all warps done with chunk k-1;
                           // slot (k+3)%4 == (k-1)%4 is safe to overwrite.
        if (k + 3 < nk) load_stage((k + 3) % NSTAGE, k + 3);
        CP_COMMIT();

        const uint32_t sa = sb + (k % NSTAGE) * STAGE_SZ;
        const uint32_t sbm = sa + 128 * ROWB;

        #pragma unroll
        for (int ks = 0; ks < 4; ks++) {
            uint32_t a[2][4], bfr[2][4];
            const uint32_t ac = (ks * 2 + acsel) * 16;
            #pragma unroll
            for (int i = 0; i < 2; i++)
                ldm4(a[i][0], a[i][1], a[i][2], a[i][3],
                     sa + (arow + i * 16) * ROWB + ac);
            const uint32_t bc = (ks * 2 + bcsel) * 16;
            #pragma unroll
            for (int j = 0; j < 2; j++)
                ldm4(bfr[j][0], bfr[j][1], bfr[j][2], bfr[j][3],
                     sbm + (brow + j * 16) * ROWB + bc);
            if (k < n1) {
                #pragma unroll
                for (int i = 0; i < 2; i++)
                    #pragma unroll
                    for (int jn = 0; jn < 4; jn++)
                        mma16832(acc0[i][jn], a[i],
                                 bfr[jn >> 1][(jn & 1) * 2], bfr[jn >> 1][(jn & 1) * 2 + 1]);
            } else {
                #pragma unroll
                for (int i = 0; i < 2; i++)
                    #pragma unroll
                    for (int jn = 0; jn < 4; jn++)
                        mma16832(acc1[i][jn], a[i],
                                 bfr[jn >> 1][(jn & 1) * 2], bfr[jn >> 1][(jn & 1) * 2 + 1]);
            }
        }
    }

    // -------- epilogue --------
    const int mb = m0 + wm0 + (lane >> 2);
    const int nb = n0 + wn0 + (lane & 3) * 2;
    #pragma unroll
    for (int i = 0; i < 2; i++) {
        #pragma unroll
        for (int half = 0; half < 2; half++) {
            const int m = mb + i * 16 + half * 8;
            const float sAm = sAarr[z * sAstr + m] * scale;
            const float br = bias_row ? bias_row[m] : 0.f;
            #pragma unroll
            for (int jn = 0; jn < 4; jn++) {
                const int n = nb + jn * 8;
                float f0 = (float)acc0[i][jn][half * 2 + 0]
                         + (float)acc1[i][jn][half * 2 + 0] * INV252;
                float f1 = (float)acc0[i][jn][half * 2 + 1]
                         + (float)acc1[i][jn][half * 2 + 1] * INV252;
                float v0 = f0 * sAm * sBarr[z * sBstr + n] + br;
                float v1 = f1 * sAm * sBarr[z * sBstr + n + 1] + br;
                if (bias_col) { v0 += bias_col[n]; v1 += bias_col[n + 1]; }
                if (EPI == 0) {
                    *(float2*)&Cf[(size_t)z * sC + (size_t)m * ldc + n] = make_float2(v0, v1);
                } else {
                    float q0 = fminf(fmaxf(v0 * SSCALE, -32000.f), 32000.f);
                    float q1 = fminf(fmaxf(v1 * SSCALE, -32000.f), 32000.f);
                    short2 o;
                    o.x = (short)(int)rintf(q0);
                    o.y = (short)(int)rintf(q1);
                    *(short2*)&Cs[(size_t)z * sC + (size_t)m * ldc + n] = o;
                }
            }
        }
    }
}

// -------------------- quantization helpers --------------------------------
__device__ __forceinline__ float clamp127(float q) {
    return fminf(127.f, fmaxf(-127.f, q));
}

__device__ __forceinline__ void rowquant_body(const float* __restrict__ src, int len,
                                              int8_t* __restrict__ dst,
                                              float* __restrict__ sOut)
{
    const int t = threadIdx.x;
    float m = 0.f;
    for (int i = t; i < len; i += 256) m = fmaxf(m, fabsf(src[i]));
    #pragma unroll
    for (int o = 16; o > 0; o >>= 1) m = fmaxf(m, __shfl_xor_sync(~0u, m, o));
    __shared__ float sm[8];
    if ((t & 31) == 0) sm[t >> 5] = m;
    __syncthreads();
    float mm = sm[0];
    #pragma unroll
    for (int i = 1; i < 8; i++) mm = fmaxf(mm, sm[i]);

    const float s1 = mm * (1.f / 127.f);
    const float i1 = (mm > 0.f) ? (127.f / mm) : 0.f;
    const float i2 = i1 * 252.f;

    for (int i = t; i < len; i += 256) {
        float x = src[i];
        float q1 = clamp127(rintf(x * i1));
        float r = x - q1 * s1;
        float q2 = clamp127(rintf(r * i2));
        dst[i] = (int8_t)(int)q1;
        dst[len + i] = (int8_t)(int)q2;
    }
    if (t == 0) *sOut = s1;
}

__global__ void __launch_bounds__(256)
rowquantW(const float* __restrict__ Wq, const float* __restrict__ Wk,
          const float* __restrict__ Wv,
          int8_t* __restrict__ Wq2, int8_t* __restrict__ Wk2, int8_t* __restrict__ Wv2,
          float* __restrict__ sWq, float* __restrict__ sWk, float* __restrict__ sWv)
{
    const int r = blockIdx.x;
    const float* src; int8_t* dst; float* sOut;
    if (r < CQK)            { src = Wq + (size_t)r * CIN;          dst = Wq2 + (size_t)r * 2 * CIN;          sOut = sWq + r; }
    else if (r < 2 * CQK)   { int rr = r - CQK;   src = Wk + (size_t)rr * CIN; dst = Wk2 + (size_t)rr * 2 * CIN; sOut = sWk + rr; }
    else                    { int rr = r - 2*CQK; src = Wv + (size_t)rr * CIN; dst = Wv2 + (size_t)rr * 2 * CIN; sOut = sWv + rr; }
    rowquant_body(src, CIN, dst, sOut);
}

__global__ void __launch_bounds__(256)
rowquantQK(const float* __restrict__ Qf, const float* __restrict__ Kf,
           int8_t* __restrict__ Q2, int8_t* __restrict__ K2,
           float* __restrict__ sQ, float* __restrict__ sK)
{
    const size_t r = blockIdx.x;
    const size_t nrows = (size_t)NB * NPIX;
    if (r < nrows)
        rowquant_body(Qf + r * CQK, CQK, Q2 + r * 2 * CQK, sQ + r);
    else {
        const size_t rr = r - nrows;
        rowquant_body(Kf + rr * CQK, CQK, K2 + rr * 2 * CQK, sK + rr);
    }
}

__global__ void __launch_bounds__(256)
rowquantV(const float* __restrict__ Vf, int8_t* __restrict__ V2, float* __restrict__ sV)
{
    const size_t r = blockIdx.x;
    rowquant_body(Vf + r * NPIX, NPIX, V2 + r * 2 * NPIX, sV + r);
}

// Chunked column-max with atomicMax (non-negative floats as ints: monotone;
// deterministic across graph replays). grid (NPIX/256, NB, 8).
__global__ void __launch_bounds__(256)
colmax8(const float* __restrict__ Xq, const float* __restrict__ Xk,
        float* __restrict__ sXq, float* __restrict__ sXk)
{
    const int n = blockIdx.x * 256 + threadIdx.x;
    const int b = blockIdx.y;
    const int zz = blockIdx.z;
    const float* X = (zz & 1) ? Xk : Xq;
    float* sX = (zz & 1) ? sXk : sXq;
    const int c0 = (zz >> 1) * (CIN / 4);
    const float* p = X + (size_t)b * CIN * NPIX + (size_t)c0 * NPIX + n;
    float m = 0.f;
    for (int ci = 0; ci < CIN / 4; ci++) m = fmaxf(m, fabsf(p[(size_t)ci * NPIX]));
    atomicMax((int*)&sX[b * NPIX + n], __float_as_int(m * (1.f / 127.f)));
}

// Merged transpose + quantize for both inputs: grid (NPIX/32, CIN/32, 2*NB)
__global__ void __launch_bounds__(256)
transpose_quant2(const float* __restrict__ Xq, const float* __restrict__ Xk,
                 const float* __restrict__ sXq, const float* __restrict__ sXk,
                 int8_t* __restrict__ Xq2, int8_t* __restrict__ Xk2)
{
    __shared__ float t[32][33];
    const int zz = blockIdx.z;
    const int b = zz & (NB - 1);
    const int which = zz >> 2;
    const float* X = which ? Xk : Xq;
    const float* sX = which ? sXk : sXq;
    int8_t* X2 = which ? Xk2 : Xq2;

    const int n0 = blockIdx.x * 32, c0 = blockIdx.y * 32;
    const int tx = threadIdx.x & 31, ty = threadIdx.x >> 5;
    const float* Xb = X + (size_t)b * CIN * NPIX;
    #pragma unroll
    for (int r = 0; r < 4; r++)
        t[ty + r * 8][tx] = Xb[(size_t)(c0 + ty + r * 8) * NPIX + n0 + tx];
    __syncthreads();
    const size_t ob = (size_t)b * NPIX * 2 * CIN;
    #pragma unroll
    for (int r = 0; r < 4; r++) {
        const int n = n0 + ty + r * 8;
        const int c = c0 + tx;
        const float v = t[tx][ty + r * 8];
        const float s1 = sX[b * NPIX + n];
        const float i1 = (s1 > 0.f) ? (1.f / s1) : 0.f;
        float q1 = clamp127(rintf(v * i1));
        float rr = v - q1 * s1;
        float q2 = clamp127(rintf(rr * i1 * 252.f));
        const size_t row = ob + (size_t)n * (2 * CIN);
        X2[row + c] = (int8_t)(int)q1;
        X2[row + CIN + c] = (int8_t)(int)q2;
    }
}

// -------- softmax: int16 S rows -> int8 attn [q1|q2] + scale ---------------
__global__ void __launch_bounds__(256)
softmax2_q(const int16_t* __restrict__ S, int8_t* __restrict__ A2,
           float* __restrict__ sAt)
{
    const size_t rb = (size_t)blockIdx.x * NPIX;
    const int16_t* row = S + rb;
    int8_t* orow = A2 + (size_t)blockIdx.x * (2 * NPIX);
    const int t = threadIdx.x;
    float v[16];
    float m = -1e30f;
    #pragma unroll
    for (int i = 0; i < 16; i++) {
        v[i] = (float)row[t + i * 256] * INVSSCALE;
        m = fmaxf(m, v[i]);
    }
    #pragma unroll
    for (int o = 16; o > 0; o >>= 1) m = fmaxf(m, __shfl_xor_sync(~0u, m, o));
    __shared__ float smax[8], ssum[8];
    if ((t & 31) == 0) smax[t >> 5] = m;
    __syncthreads();
    float mm = smax[0];
    #pragma unroll
    for (int i = 1; i < 8; i++) mm = fmaxf(mm, smax[i]);
    float s = 0.f;
    #pragma unroll
    for (int i = 0; i < 16; i++) { v[i] = __expf(v[i] - mm); s += v[i]; }
    #pragma unroll
    for (int o = 16; o > 0; o >>= 1) s += __shfl_xor_sync(~0u, s, o);
    if ((t & 31) == 0) ssum[t >> 5] = s;
    __syncthreads();
    float tot = 0.f;
    #pragma unroll
    for (int i = 0; i < 8; i++) tot += ssum[i];
    const float inv = 1.0f / tot;

    #pragma unroll
    for (int i = 0; i < 16; i++) {
        const int k = t + i * 256;
        float f = v[i] * 127.f;
        float q1 = clamp127(rintf(f));
        float q2 = clamp127(rintf((f - q1) * 252.f));
        orow[k] = (int8_t)(int)q1;
        orow[NPIX + k] = (int8_t)(int)q2;
    }
    if (t == 0) sAt[blockIdx.x] = inv * (1.f / 127.f);
}

// ------------------------------- host -------------------------------------
extern "C" void kernel_launch(void* const* d_in, const int* in_sizes, int n_in,
                              void* d_out, int out_size)
{
    const float* qfeat = (const float*)d_in[0];
    const float* bq_unused = nullptr; (void)bq_unused;
    const float* kfeat = (const float*)d_in[1];
    const float* Wq = (const float*)d_in[2];
    const float* bq = (const float*)d_in[3];
    const float* Wk = (const float*)d_in[4];
    const float* bk = (const float*)d_in[5];
    const float* Wv = (const float*)d_in[6];
    const float* bv = (const float*)d_in[7];
    float* out = (float*)d_out;

    void *Xq2, *Xk2, *Wq2, *Wk2, *Wv2, *Qf, *Kf, *Vf, *Q2, *K2, *V2, *Sd, *A2;
    void *sXq, *sXk, *sWq, *sWk, *sWv, *sQ, *sK, *sV, *sAt;
    cudaGetSymbolAddress(&Xq2, g_Xq2);
    cudaGetSymbolAddress(&Xk2, g_Xk2);
    cudaGetSymbolAddress(&Wq2, g_Wq2);
    cudaGetSymbolAddress(&Wk2, g_Wk2);
    cudaGetSymbolAddress(&Wv2, g_Wv2);
    cudaGetSymbolAddress(&Qf, g_Qf);
    cudaGetSymbolAddress(&Kf, g_Kf);
    cudaGetSymbolAddress(&Vf, g_Vf);
    cudaGetSymbolAddress(&Q2, g_Q2);
    cudaGetSymbolAddress(&K2, g_K2);
    cudaGetSymbolAddress(&V2, g_V2);
    cudaGetSymbolAddress(&Sd, g_S);
    cudaGetSymbolAddress(&A2, g_A2);
    cudaGetSymbolAddress(&sXq, g_sXq);
    cudaGetSymbolAddress(&sXk, g_sXk);
    cudaGetSymbolAddress(&sWq, g_sWq);
    cudaGetSymbolAddress(&sWk, g_sWk);
    cudaGetSymbolAddress(&sWv, g_sWv);
    cudaGetSymbolAddress(&sQ, g_sQ);
    cudaGetSymbolAddress(&sK, g_sK);
    cudaGetSymbolAddress(&sV, g_sV);
    cudaGetSymbolAddress(&sAt, g_sAt);

    cudaFuncSetAttribute(gemm_s8<0>, cudaFuncAttributeMaxDynamicSharedMemorySize, GSMEM);
    cudaFuncSetAttribute(gemm_s8<1>, cudaFuncAttributeMaxDynamicSharedMemorySize, GSMEM);

    // 1) weights quantization (merged)
    rowquantW<<<2 * CQK + COUT, 256>>>(Wq, Wk, Wv,
        (int8_t*)Wq2, (int8_t*)Wk2, (int8_t*)Wv2,
        (float*)sWq, (float*)sWk, (float*)sWv);

    // 2) column maxima (chunked + atomicMax)
    colmax8<<<dim3(NPIX / 256, NB, 8), 256>>>(qfeat, kfeat, (float*)sXq, (float*)sXk);

    // 3) transpose + quantize both inputs (merged)
    transpose_quant2<<<dim3(NPIX / 32, CIN / 32, 2 * NB), 256>>>(
        qfeat, kfeat, (const float*)sXq, (const float*)sXk,
        (int8_t*)Xq2, (int8_t*)Xk2);

    // 4) Q proj: Qf[b][n][c] = Xq2 . Wq2^T + bq  (M=4096, N=256, K=512)
    gemm_s8<0><<<dim3(CQK / 64, NPIX / 128, NB), 256, GSMEM>>>(
        (const int8_t*)Xq2, (size_t)NPIX * 2 * CIN,
        (const int8_t*)Wq2, 0, CIN,
        (float*)Qf, nullptr, (size_t)CQK, (size_t)NPIX * CQK,
        (const float*)sXq, (size_t)NPIX, (const float*)sWq, 0,
        nullptr, bq, 1.0f);

    // 5) K proj  <- profiled launch slot
    gemm_s8<0><<<dim3(CQK / 64, NPIX / 128, NB), 256, GSMEM>>>(
        (const int8_t*)Xk2, (size_t)NPIX * 2 * CIN,
        (const int8_t*)Wk2, 0, CIN,
        (float*)Kf, nullptr, (size_t)CQK, (size_t)NPIX * CQK,
        (const float*)sXk, (size_t)NPIX, (const float*)sWk, 0,
        nullptr, bk, 1.0f);

    // 6) V proj: Vf[b][o][m] = Wv2 . Xk2^T + bv  (M=512, N=4096, K=512)
    gemm_s8<0><<<dim3(NPIX / 64, COUT / 128, NB), 256, GSMEM>>>(
        (const int8_t*)Wv2, 0,
        (const int8_t*)Xk2, (size_t)NPIX * 2 * CIN, CIN,
        (float*)Vf, nullptr, (size_t)NPIX, (size_t)COUT * NPIX,
        (const float*)sWv, 0, (const float*)sXk, (size_t)NPIX,
        bv, nullptr, 1.0f);

    // 7) quantize Q+K (merged) and V
    rowquantQK<<<2 * NB * NPIX, 256>>>((const float*)Qf, (const float*)Kf,
        (int8_t*)Q2, (int8_t*)K2, (float*)sQ, (float*)sK);
    rowquantV<<<NB * COUT, 256>>>((const float*)Vf, (int8_t*)V2, (float*)sV);

    // 8) sim: S = int16( (1/16) Q2 . K2^T * SSCALE )  (M=N=4096, K=256)
    gemm_s8<1><<<dim3(NPIX / 64, NPIX / 128, NB), 256, GSMEM>>>(
        (const int8_t*)Q2, (size_t)NPIX * 2 * CQK,
        (const int8_t*)K2, (size_t)NPIX * 2 * CQK, CQK,
        nullptr, (int16_t*)Sd, (size_t)NPIX, (size_t)NPIX * NPIX,
        (const float*)sQ, (size_t)NPIX, (const float*)sK, (size_t)NPIX,
        nullptr, nullptr, 0.0625f);

    // 9) softmax -> int8 attn [q1|q2] + scales
    softmax2_q<<<NB * NPIX, 256>>>((const int16_t*)Sd, (int8_t*)A2, (float*)sAt);

    // 10) ctx: out = V2 . A2^T  (M=512, N=4096, K=4096)
    gemm_s8<0><<<dim3(NPIX / 64, COUT / 128, NB), 256, GSMEM>>>(
        (const int8_t*)V2, (size_t)COUT * 2 * NPIX,
        (const int8_t*)A2, (size_t)NPIX * 2 * NPIX, NPIX,
        out, nullptr, (size_t)NPIX, (size_t)COUT * NPIX,
        (const float*)sV, (size_t)COUT, (const float*)sAt, (size_t)NPIX,
        nullptr, nullptr, 1.0f);
}

// round 15
// speedup vs baseline: 3.3134x; 1.0061x over previous
#include <cuda_runtime.h>
#include <cstdint>
#include <cstddef>

#define NB    4
#define CIN   512
#define NPIX  4096
#define CQK   256
#define COUT  512

#define ROWB    144           // padded smem row bytes (128B data + 16B pad)
#define INV252  (1.0f/252.0f)
#define SSCALE  2048.0f
#define INVSSCALE (1.0f/2048.0f)

// -------------------- scratch (device globals) ----------------------------
__device__ int8_t  g_Xq2[(size_t)NB*NPIX*2*CIN];
__device__ int8_t  g_Xk2[(size_t)NB*NPIX*2*CIN];
__device__ int8_t  g_Wq2[CQK*2*CIN];
__device__ int8_t  g_Wk2[CQK*2*CIN];
__device__ int8_t  g_Wv2[COUT*2*CIN];
__device__ float   g_Qf[(size_t)NB*NPIX*CQK];
__device__ float   g_Kf[(size_t)NB*NPIX*CQK];
__device__ float   g_Vf[(size_t)NB*COUT*NPIX];
__device__ int8_t  g_Q2[(size_t)NB*NPIX*2*CQK];
__device__ int8_t  g_K2[(size_t)NB*NPIX*2*CQK];
__device__ int8_t  g_V2[(size_t)NB*COUT*2*NPIX];
__device__ int16_t g_S [(size_t)NB*NPIX*NPIX];
__device__ int8_t  g_A2[(size_t)NB*NPIX*2*NPIX];
__device__ float g_sXq[NB*NPIX], g_sXk[NB*NPIX];
__device__ float g_sWq[CQK], g_sWk[CQK], g_sWv[COUT];
__device__ float g_sQ[NB*NPIX], g_sK[NB*NPIX], g_sV[NB*COUT], g_sAt[NB*NPIX];

// -------------------- PTX helpers -----------------------------------------
__device__ __forceinline__ uint32_t s2u(const void* p) {
    uint32_t a;
    asm("{ .reg .u64 t; cvta.to.shared.u64 t, %1; cvt.u32.u64 %0, t; }" : "=r"(a) : "l"(p));
    return a;
}
__device__ __forceinline__ void cp16(uint32_t s, const void* g) {
    asm volatile("cp.async.cg.shared.global [%0], [%1], 16;" :: "r"(s), "l"(g));
}
#define CP_COMMIT() asm volatile("cp.async.commit_group;" ::: "memory")

__device__ __forceinline__ void ldm4(uint32_t& r0, uint32_t& r1, uint32_t& r2, uint32_t& r3,
                                     uint32_t a) {
    asm volatile("ldmatrix.sync.aligned.m8n8.x4.shared.b16 {%0,%1,%2,%3}, [%4];"
                 : "=r"(r0), "=r"(r1), "=r"(r2), "=r"(r3) : "r"(a));
}
__device__ __forceinline__ void mma16832(int* d, const uint32_t* a, uint32_t b0, uint32_t b1) {
    asm volatile(
      "mma.sync.aligned.m16n8k32.row.col.s32.s8.s8.s32 "
      "{%0,%1,%2,%3},{%4,%5,%6,%7},{%8,%9},{%0,%1,%2,%3};"
      : "+r"(d[0]), "+r"(d[1]), "+r"(d[2]), "+r"(d[3])
      : "r"(a[0]), "r"(a[1]), "r"(a[2]), "r"(a[3]), "r"(b0), "r"(b1));
}

// -------------------- canonical int8 Ozaki GEMM ---------------------------
// D[M,N] = scale * sigA[m]*sigB[n]*(acc0 + acc1/252) + biases.
// Physical rows [q1|q2] (2K bytes); logical 128B chunks A:[q1|q1|q2],
// B:[q1|q2|q1] via remap; chunks < K/128 -> acc0, rest -> acc1.
// TM=128: 256 thr, 8 warps 4x2, NSTAGE 4, 2 CTAs/SM.
// TM=64 : 128 thr, 4 warps 2x2, NSTAGE 3, 4 CTAs/SM (4 independent barrier
//         domains per SM -> latency hiding across CTAs).
// EPI 0: fp32 out.  EPI 1: int16 out (value * SSCALE, clamped).
template<int EPI, int TM>
__global__ void __launch_bounds__(TM == 128 ? 256 : 128, TM == 128 ? 2 : 4)
gemm_s8(const int8_t* __restrict__ A, size_t sA,
        const int8_t* __restrict__ B, size_t sB,
        int K,
        float* __restrict__ Cf, int16_t* __restrict__ Cs, size_t ldc, size_t sC,
        const float* __restrict__ sAarr, size_t sAstr,
        const float* __restrict__ sBarr, size_t sBstr,
        const float* __restrict__ bias_row, const float* __restrict__ bias_col,
        float scale)
{
    constexpr int THREADS = (TM == 128) ? 256 : 128;
    constexpr int NST     = (TM == 128) ? 4 : 3;
    constexpr int STG     = (TM + 64) * ROWB;
    constexpr int LITER   = (TM + 64) * 8 / THREADS;

    extern __shared__ __align__(128) char smem[];
    const uint32_t sb = s2u(smem);
    const int tid = threadIdx.x, lane = tid & 31, wid = tid >> 5;
    const int wm0 = (TM == 128) ? (wid & 3) * 32 : (wid & 1) * 32;
    const int wn0 = (TM == 128) ? (wid >> 2) * 32 : (wid >> 1) * 32;
    const int m0 = blockIdx.y * TM, n0 = blockIdx.x * 64, z = blockIdx.z;

    const int n1 = K / 128;
    const int nk = 3 * n1;
    const int rowlen = 2 * K;

    A += (size_t)z * sA + (size_t)m0 * rowlen;
    B += (size_t)z * sB + (size_t)n0 * rowlen;

    auto load_stage = [&](int st, int kc) {
        const int ca = (kc < n1) ? kc : kc - n1;          // A: [q1|q1|q2]
        const int cb = (kc < 2 * n1) ? kc : kc - 2 * n1;  // B: [q1|q2|q1]
        const int8_t* ga = A + (size_t)ca * 128;
        const int8_t* gb = B + (size_t)cb * 128;
        uint32_t sa = sb + st * STG;
        uint32_t sbm = sa + TM * ROWB;
        #pragma unroll
        for (int i = 0; i < LITER; i++) {
            const int idx = tid + i * THREADS;   // (TM+64) rows x 8 chunks
            const int row = idx >> 3, ch = idx & 7;
            if (row < TM)
                cp16(sa + row * ROWB + ch * 16, ga + (size_t)row * rowlen + ch * 16);
            else
                cp16(sbm + (row - TM) * ROWB + ch * 16,
                     gb + (size_t)(row - TM) * rowlen + ch * 16);
        }
    };

    int acc0[2][4][4], acc1[2][4][4];
    #pragma unroll
    for (int i = 0; i < 2; i++)
        #pragma unroll
        for (int j = 0; j < 4; j++)
            #pragma unroll
            for (int q = 0; q < 4; q++) { acc0[i][j][q] = 0; acc1[i][j][q] = 0; }

    #pragma unroll
    for (int s = 0; s < NST - 1; s++) { load_stage(s, s); CP_COMMIT(); }

    const int arow = wm0 + (lane & 15);
    const int acsel = (lane >> 4);
    const int brow = wn0 + (lane & 7) + ((lane >> 4) & 1) * 8;
    const int bcsel = (lane >> 3) & 1;

    for (int k = 0; k < nk; k++) {
        // committed groups so far: 0..k+NST-2; wait NST-2 -> chunks <= k done
        if (NST == 4) asm volatile("cp.async.wait_group 2;" ::: "memory");
        else          asm volatile("cp.async.wait_group 1;" ::: "memory");
        __syncthreads();   // all warps done reading slot (k-1)%NST == (k+NST-1)%NST
        if (k + NST - 1 < nk) load_stage((k + NST - 1) % NST, k + NST - 1);
        CP_COMMIT();

        const uint32_t sa = sb + (k % NST) * STG;
        const uint32_t sbm = sa + TM * ROWB;

        #pragma unroll
        for (int ks = 0; ks < 4; ks++) {
            uint32_t a[2][4], bfr[2][4];
            const uint32_t ac = (ks * 2 + acsel) * 16;
            #pragma unroll
            for (int i = 0; i < 2; i++)
                ldm4(a[i][0], a[i][1], a[i][2], a[i][3],
                     sa + (arow + i * 16) * ROWB + ac);
            const uint32_t bc = (ks * 2 + bcsel) * 16;
            #pragma unroll
            for (int j = 0; j < 2; j++)
                ldm4(bfr[j][0], bfr[j][1], bfr[j][2], bfr[j][3],
                     sbm + (brow + j * 16) * ROWB + bc);
            if (k < n1) {
                #pragma unroll
                for (int i = 0; i < 2; i++)
                    #pragma unroll
                    for (int jn = 0; jn < 4; jn++)
                        mma16832(acc0[i][jn], a[i],
                                 bfr[jn >> 1][(jn & 1) * 2], bfr[jn >> 1][(jn & 1) * 2 + 1]);
            } else {
                #pragma unroll
                for (int i = 0; i < 2; i++)
                    #pragma unroll
                    for (int jn = 0; jn < 4; jn++)
                        mma16832(acc1[i][jn], a[i],
                                 bfr[jn >> 1][(jn & 1) * 2], bfr[jn >> 1][(jn & 1) * 2 + 1]);
            }
        }
    }

    // -------- epilogue --------
    const int mb = m0 + wm0 + (lane >> 2);
    const int nb = n0 + wn0 + (lane & 3) * 2;
    #pragma unroll
    for (int i = 0; i < 2; i++) {
        #pragma unroll
        for (int half = 0; half < 2; half++) {
            const int m = mb + i * 16 + half * 8;
            const float sAm = sAarr[z * sAstr + m] * scale;
            const float br = bias_row ? bias_row[m] : 0.f;
            #pragma unroll
            for (int jn = 0; jn < 4; jn++) {
                const int n = nb + jn * 8;
                float f0 = (float)acc0[i][jn][half * 2 + 0]
                         + (float)acc1[i][jn][half * 2 + 0] * INV252;
                float f1 = (float)acc0[i][jn][half * 2 + 1]
                         + (float)acc1[i][jn][half * 2 + 1] * INV252;
                float v0 = f0 * sAm * sBarr[z * sBstr + n] + br;
                float v1 = f1 * sAm * sBarr[z * sBstr + n + 1] + br;
                if (bias_col) { v0 += bias_col[n]; v1 += bias_col[n + 1]; }
                if (EPI == 0) {
                    *(float2*)&Cf[(size_t)z * sC + (size_t)m * ldc + n] = make_float2(v0, v1);
                } else {
                    float q0 = fminf(fmaxf(v0 * SSCALE, -32000.f), 32000.f);
                    float q1 = fminf(fmaxf(v1 * SSCALE, -32000.f), 32000.f);
                    short2 o;
                    o.x = (short)(int)rintf(q0);
                    o.y = (short)(int)rintf(q1);
                    *(short2*)&Cs[(size_t)z * sC + (size_t)m * ldc + n] = o;
                }
            }
        }
    }
}

// -------------------- quantization helpers --------------------------------
__device__ __forceinline__ float clamp127(float q) {
    return fminf(127.f, fmaxf(-127.f, q));
}

__device__ __forceinline__ void rowquant_body(const float* __restrict__ src, int len,
                                              int8_t* __restrict__ dst,
                                              float* __restrict__ sOut)
{
    const int t = threadIdx.x;
    float m = 0.f;
    for (int i = t; i < len; i += 256) m = fmaxf(m, fabsf(src[i]));
    #pragma unroll
    for (int o = 16; o > 0; o >>= 1) m = fmaxf(m, __shfl_xor_sync(~0u, m, o));
    __shared__ float sm[8];
    if ((t & 31) == 0) sm[t >> 5] = m;
    __syncthreads();
    float mm = sm[0];
    #pragma unroll
    for (int i = 1; i < 8; i++) mm = fmaxf(mm, sm[i]);

    const float s1 = mm * (1.f / 127.f);
    const float i1 = (mm > 0.f) ? (127.f / mm) : 0.f;
    const float i2 = i1 * 252.f;

    for (int i = t; i < len; i += 256) {
        float x = src[i];
        float q1 = clamp127(rintf(x * i1));
        float r = x - q1 * s1;
        float q2 = clamp127(rintf(r * i2));
        dst[i] = (int8_t)(int)q1;
        dst[len + i] = (int8_t)(int)q2;
    }
    if (t == 0) *sOut = s1;
}

__global__ void __launch_bounds__(256)
rowquantW(const float* __restrict__ Wq, const float* __restrict__ Wk,
          const float* __restrict__ Wv,
          int8_t* __restrict__ Wq2, int8_t* __restrict__ Wk2, int8_t* __restrict__ Wv2,
          float* __restrict__ sWq, float* __restrict__ sWk, float* __restrict__ sWv)
{
    const int r = blockIdx.x;
    const float* src; int8_t* dst; float* sOut;
    if (r < CQK)            { src = Wq + (size_t)r * CIN;          dst = Wq2 + (size_t)r * 2 * CIN;          sOut = sWq + r; }
    else if (r < 2 * CQK)   { int rr = r - CQK;   src = Wk + (size_t)rr * CIN; dst = Wk2 + (size_t)rr * 2 * CIN; sOut = sWk + rr; }
    else                    { int rr = r - 2*CQK; src = Wv + (size_t)rr * CIN; dst = Wv2 + (size_t)rr * 2 * CIN; sOut = sWv + rr; }
    rowquant_body(src, CIN, dst, sOut);
}

__global__ void __launch_bounds__(256)
rowquantQK(const float* __restrict__ Qf, const float* __restrict__ Kf,
           int8_t* __restrict__ Q2, int8_t* __restrict__ K2,
           float* __restrict__ sQ, float* __restrict__ sK)
{
    const size_t r = blockIdx.x;
    const size_t nrows = (size_t)NB * NPIX;
    if (r < nrows)
        rowquant_body(Qf + r * CQK, CQK, Q2 + r * 2 * CQK, sQ + r);
    else {
        const size_t rr = r - nrows;
        rowquant_body(Kf + rr * CQK, CQK, K2 + rr * 2 * CQK, sK + rr);
    }
}

__global__ void __launch_bounds__(256)
rowquantV(const float* __restrict__ Vf, int8_t* __restrict__ V2, float* __restrict__ sV)
{
    const size_t r = blockIdx.x;
    rowquant_body(Vf + r * NPIX, NPIX, V2 + r * 2 * NPIX, sV + r);
}

// Chunked column-max with atomicMax (non-negative floats as ints: monotone;
// deterministic across graph replays). grid (NPIX/256, NB, 8).
__global__ void __launch_bounds__(256)
colmax8(const float* __restrict__ Xq, const float* __restrict__ Xk,
        float* __restrict__ sXq, float* __restrict__ sXk)
{
    const int n = blockIdx.x * 256 + threadIdx.x;
    const int b = blockIdx.y;
    const int zz = blockIdx.z;
    const float* X = (zz & 1) ? Xk : Xq;
    float* sX = (zz & 1) ? sXk : sXq;
    const int c0 = (zz >> 1) * (CIN / 4);
    const float* p = X + (size_t)b * CIN * NPIX + (size_t)c0 * NPIX + n;
    float m = 0.f;
    for (int ci = 0; ci < CIN / 4; ci++) m = fmaxf(m, fabsf(p[(size_t)ci * NPIX]));
    atomicMax((int*)&sX[b * NPIX + n], __float_as_int(m * (1.f / 127.f)));
}

// Merged transpose + quantize for both inputs: grid (NPIX/32, CIN/32, 2*NB)
__global__ void __launch_bounds__(256)
transpose_quant2(const float* __restrict__ Xq, const float* __restrict__ Xk,
                 const float* __restrict__ sXq, const float* __restrict__ sXk,
                 int8_t* __restrict__ Xq2, int8_t* __restrict__ Xk2)
{
    __shared__ float t[32][33];
    const int zz = blockIdx.z;
    const int b = zz & (NB - 1);
    const int which = zz >> 2;
    const float* X = which ? Xk : Xq;
    const float* sX = which ? sXk : sXq;
    int8_t* X2 = which ? Xk2 : Xq2;

    const int n0 = blockIdx.x * 32, c0 = blockIdx.y * 32;
    const int tx = threadIdx.x & 31, ty = threadIdx.x >> 5;
    const float* Xb = X + (size_t)b * CIN * NPIX;
    #pragma unroll
    for (int r = 0; r < 4; r++)
        t[ty + r * 8][tx] = Xb[(size_t)(c0 + ty + r * 8) * NPIX + n0 + tx];
    __syncthreads();
    const size_t ob = (size_t)b * NPIX * 2 * CIN;
    #pragma unroll
    for (int r = 0; r < 4; r++) {
        const int n = n0 + ty + r * 8;
        const int c = c0 + tx;
        const float v = t[tx][ty + r * 8];
        const float s1 = sX[b * NPIX + n];
        const float i1 = (s1 > 0.f) ? (1.f / s1) : 0.f;
        float q1 = clamp127(rintf(v * i1));
        float rr = v - q1 * s1;
        float q2 = clamp127(rintf(rr * i1 * 252.f));
        const size_t row = ob + (size_t)n * (2 * CIN);
        X2[row + c] = (int8_t)(int)q1;
        X2[row + CIN + c] = (int8_t)(int)q2;
    }
}

// -------- softmax: int16 S rows -> int8 attn [q1|q2] + scale ---------------
__global__ void __launch_bounds__(256)
softmax2_q(const int16_t* __restrict__ S, int8_t* __restrict__ A2,
           float* __restrict__ sAt)
{
    const size_t rb = (size_t)blockIdx.x * NPIX;
    const int16_t* row = S + rb;
    int8_t* orow = A2 + (size_t)blockIdx.x * (2 * NPIX);
    const int t = threadIdx.x;
    float v[16];
    float m = -1e30f;
    #pragma unroll
    for (int i = 0; i < 16; i++) {
        v[i] = (float)row[t + i * 256] * INVSSCALE;
        m = fmaxf(m, v[i]);
    }
    #pragma unroll
    for (int o = 16; o > 0; o >>= 1) m = fmaxf(m, __shfl_xor_sync(~0u, m, o));
    __shared__ float smax[8], ssum[8];
    if ((t & 31) == 0) smax[t >> 5] = m;
    __syncthreads();
    float mm = smax[0];
    #pragma unroll
    for (int i = 1; i < 8; i++) mm = fmaxf(mm, smax[i]);
    float s = 0.f;
    #pragma unroll
    for (int i = 0; i < 16; i++) { v[i] = __expf(v[i] - mm); s += v[i]; }
    #pragma unroll
    for (int o = 16; o > 0; o >>= 1) s += __shfl_xor_sync(~0u, s, o);
    if ((t & 31) == 0) ssum[t >> 5] = s;
    __syncthreads();
    float tot = 0.f;
    #pragma unroll
    for (int i = 0; i < 8; i++) tot += ssum[i];
    const float inv = 1.0f / tot;

    #pragma unroll
    for (int i = 0; i < 16; i++) {
        const int k = t + i * 256;
        float f = v[i] * 127.f;
        float q1 = clamp127(rintf(f));
        float q2 = clamp127(rintf((f - q1) * 252.f));
        orow[k] = (int8_t)(int)q1;
        orow[NPIX + k] = (int8_t)(int)q2;
    }
    if (t == 0) sAt[blockIdx.x] = inv * (1.f / 127.f);
}

// ------------------------------- host -------------------------------------
extern "C" void kernel_launch(void* const* d_in, const int* in_sizes, int n_in,
                              void* d_out, int out_size)
{
    const float* qfeat = (const float*)d_in[0];
    const float* kfeat = (const float*)d_in[1];
    const float* Wq = (const float*)d_in[2];
    const float* bq = (const float*)d_in[3];
    const float* Wk = (const float*)d_in[4];
    const float* bk = (const float*)d_in[5];
    const float* Wv = (const float*)d_in[6];
    const float* bv = (const float*)d_in[7];
    float* out = (float*)d_out;

    void *Xq2, *Xk2, *Wq2, *Wk2, *Wv2, *Qf, *Kf, *Vf, *Q2, *K2, *V2, *Sd, *A2;
    void *sXq, *sXk, *sWq, *sWk, *sWv, *sQ, *sK, *sV, *sAt;
    cudaGetSymbolAddress(&Xq2, g_Xq2);
    cudaGetSymbolAddress(&Xk2, g_Xk2);
    cudaGetSymbolAddress(&Wq2, g_Wq2);
    cudaGetSymbolAddress(&Wk2, g_Wk2);
    cudaGetSymbolAddress(&Wv2, g_Wv2);
    cudaGetSymbolAddress(&Qf, g_Qf);
    cudaGetSymbolAddress(&Kf, g_Kf);
    cudaGetSymbolAddress(&Vf, g_Vf);
    cudaGetSymbolAddress(&Q2, g_Q2);
    cudaGetSymbolAddress(&K2, g_K2);
    cudaGetSymbolAddress(&V2, g_V2);
    cudaGetSymbolAddress(&Sd, g_S);
    cudaGetSymbolAddress(&A2, g_A2);
    cudaGetSymbolAddress(&sXq, g_sXq);
    cudaGetSymbolAddress(&sXk, g_sXk);
    cudaGetSymbolAddress(&sWq, g_sWq);
    cudaGetSymbolAddress(&sWk, g_sWk);
    cudaGetSymbolAddress(&sWv, g_sWv);
    cudaGetSymbolAddress(&sQ, g_sQ);
    cudaGetSymbolAddress(&sK, g_sK);
    cudaGetSymbolAddress(&sV, g_sV);
    cudaGetSymbolAddress(&sAt, g_sAt);

    const int SM64  = (64 + 64) * ROWB * 3;    // 55296
    const int SM128 = (128 + 64) * ROWB * 4;   // 110592
    cudaFuncSetAttribute((const void*)gemm_s8<0, 64>,  cudaFuncAttributeMaxDynamicSharedMemorySize, SM64);
    cudaFuncSetAttribute((const void*)gemm_s8<1, 64>,  cudaFuncAttributeMaxDynamicSharedMemorySize, SM64);
    cudaFuncSetAttribute((const void*)gemm_s8<0, 128>, cudaFuncAttributeMaxDynamicSharedMemorySize, SM128);

    // 1) weights quantization (merged)
    rowquantW<<<2 * CQK + COUT, 256>>>(Wq, Wk, Wv,
        (int8_t*)Wq2, (int8_t*)Wk2, (int8_t*)Wv2,
        (float*)sWq, (float*)sWk, (float*)sWv);

    // 2) column maxima (chunked + atomicMax)
    colmax8<<<dim3(NPIX / 256, NB, 8), 256>>>(qfeat, kfeat, (float*)sXq, (float*)sXk);

    // 3) transpose + quantize both inputs (merged)
    transpose_quant2<<<dim3(NPIX / 32, CIN / 32, 2 * NB), 256>>>(
        qfeat, kfeat, (const float*)sXq, (const float*)sXk,
        (int8_t*)Xq2, (int8_t*)Xk2);

    // 4) Q proj (TM=64): M=4096, N=256, K=512
    gemm_s8<0, 64><<<dim3(CQK / 64, NPIX / 64, NB), 128, SM64>>>(
        (const int8_t*)Xq2, (size_t)NPIX * 2 * CIN,
        (const int8_t*)Wq2, 0, CIN,
        (float*)Qf, nullptr, (size_t)CQK, (size_t)NPIX * CQK,
        (const float*)sXq, (size_t)NPIX, (const float*)sWq, 0,
        nullptr, bq, 1.0f);

    // 5) K proj  <- profiled launch slot (TM=64)
    gemm_s8<0, 64><<<dim3(CQK / 64, NPIX / 64, NB), 128, SM64>>>(
        (const int8_t*)Xk2, (size_t)NPIX * 2 * CIN,
        (const int8_t*)Wk2, 0, CIN,
        (float*)Kf, nullptr, (size_t)CQK, (size_t)NPIX * CQK,
        (const float*)sXk, (size_t)NPIX, (const float*)sWk, 0,
        nullptr, bk, 1.0f);

    // 6) V proj (TM=64): M=512, N=4096, K=512
    gemm_s8<0, 64><<<dim3(NPIX / 64, COUT / 64, NB), 128, SM64>>>(
        (const int8_t*)Wv2, 0,
        (const int8_t*)Xk2, (size_t)NPIX * 2 * CIN, CIN,
        (float*)Vf, nullptr, (size_t)NPIX, (size_t)COUT * NPIX,
        (const float*)sWv, 0, (const float*)sXk, (size_t)NPIX,
        bv, nullptr, 1.0f);

    // 7) quantize Q+K (merged) and V
    rowquantQK<<<2 * NB * NPIX, 256>>>((const float*)Qf, (const float*)Kf,
        (int8_t*)Q2, (int8_t*)K2, (float*)sQ, (float*)sK);
    rowquantV<<<NB * COUT, 256>>>((const float*)Vf, (int8_t*)V2, (float*)sV);

    // 8) sim (TM=64): S = int16( (1/16) Q2 . K2^T * SSCALE ), M=N=4096, K=256
    gemm_s8<1, 64><<<dim3(NPIX / 64, NPIX / 64, NB), 128, SM64>>>(
        (const int8_t*)Q2, (size_t)NPIX * 2 * CQK,
        (const int8_t*)K2, (size_t)NPIX * 2 * CQK, CQK,
        nullptr, (int16_t*)Sd, (size_t)NPIX, (size_t)NPIX * NPIX,
        (const float*)sQ, (size_t)NPIX, (const float*)sK, (size_t)NPIX,
        nullptr, nullptr, 0.0625f);

    // 9) softmax -> int8 attn [q1|q2] + scales
    softmax2_q<<<NB * NPIX, 256>>>((const int16_t*)Sd, (int8_t*)A2, (float*)sAt);

    // 10) ctx (TM=128, L2-heavy): out = V2 . A2^T, M=512, N=4096, K=4096
    gemm_s8<0, 128><<<dim3(NPIX / 64, COUT / 128, NB), 256, SM128>>>(
        (const int8_t*)V2, (size_t)COUT * 2 * NPIX,
        (const int8_t*)A2, (size_t)NPIX * 2 * NPIX, NPIX,
        out, nullptr, (size_t)NPIX, (size_t)COUT * NPIX,
        (const float*)sV, (size_t)COUT, (const float*)sAt, (size_t)NPIX,
        nullptr, nullptr, 1.0f);
}